// round 1
// baseline (speedup 1.0000x reference)
#include <cuda_runtime.h>
#include <math.h>

#define BSZ  4
#define SEQ  2048
#define DIMM 768
#define NH   12
#define DH   64
#define NTOK (BSZ*SEQ)   // 8192

// Scratch (device globals: no allocation allowed in kernel_launch)
__device__ float g_q[(size_t)NTOK*DIMM];
__device__ float g_k[(size_t)NTOK*DIMM];
__device__ float g_v[(size_t)NTOK*DIMM];
__device__ float g_ctx[(size_t)NTOK*DIMM];

// ---------------------------------------------------------------------------
// NT GEMM with bias: C[M,N] = A[M,K] @ B[N,K]^T + bias[N]
// BM=BN=128, BK=16, 256 threads, 8x8 microtile per thread.
// ---------------------------------------------------------------------------
#define GBM 128
#define GBN 128
#define GBK 16

__global__ __launch_bounds__(256)
void gemm_nt_bias(const float* __restrict__ A, const float* __restrict__ Bm,
                  const float* __restrict__ bias, float* __restrict__ C,
                  int M, int N, int K)
{
    __shared__ float As[GBK][GBM + 4];
    __shared__ float Bs[GBK][GBN + 4];

    const int bm  = blockIdx.y * GBM;
    const int bn  = blockIdx.x * GBN;
    const int tid = threadIdx.x;
    const int tx  = tid & 15;   // 0..15 -> N microtile
    const int ty  = tid >> 4;   // 0..15 -> M microtile

    float acc[8][8];
#pragma unroll
    for (int i = 0; i < 8; i++)
#pragma unroll
        for (int j = 0; j < 8; j++) acc[i][j] = 0.f;

    const int lrow = tid >> 2;  // 0..63
    const int lkq  = tid & 3;   // 0..3 (k-quad)

    for (int k0 = 0; k0 < K; k0 += GBK) {
#pragma unroll
        for (int hh = 0; hh < 2; hh++) {
            int r = lrow + hh * 64;
            float4 va = *reinterpret_cast<const float4*>(
                &A[(size_t)(bm + r) * K + k0 + lkq * 4]);
            As[lkq*4+0][r] = va.x; As[lkq*4+1][r] = va.y;
            As[lkq*4+2][r] = va.z; As[lkq*4+3][r] = va.w;
            float4 vb = *reinterpret_cast<const float4*>(
                &Bm[(size_t)(bn + r) * K + k0 + lkq * 4]);
            Bs[lkq*4+0][r] = vb.x; Bs[lkq*4+1][r] = vb.y;
            Bs[lkq*4+2][r] = vb.z; Bs[lkq*4+3][r] = vb.w;
        }
        __syncthreads();

#pragma unroll
        for (int kk = 0; kk < GBK; kk++) {
            float a[8], b[8];
            *reinterpret_cast<float4*>(a)     = *reinterpret_cast<const float4*>(&As[kk][ty*8]);
            *reinterpret_cast<float4*>(a + 4) = *reinterpret_cast<const float4*>(&As[kk][ty*8+4]);
            *reinterpret_cast<float4*>(b)     = *reinterpret_cast<const float4*>(&Bs[kk][tx*8]);
            *reinterpret_cast<float4*>(b + 4) = *reinterpret_cast<const float4*>(&Bs[kk][tx*8+4]);
#pragma unroll
            for (int i = 0; i < 8; i++)
#pragma unroll
                for (int j = 0; j < 8; j++)
                    acc[i][j] = fmaf(a[i], b[j], acc[i][j]);
        }
        __syncthreads();
    }

#pragma unroll
    for (int i = 0; i < 8; i++) {
        int row = bm + ty * 8 + i;
#pragma unroll
        for (int j = 0; j < 8; j += 4) {
            int col = bn + tx * 8 + j;
            float4 v;
            v.x = acc[i][j]   + bias[col];
            v.y = acc[i][j+1] + bias[col+1];
            v.z = acc[i][j+2] + bias[col+2];
            v.w = acc[i][j+3] + bias[col+3];
            *reinterpret_cast<float4*>(&C[(size_t)row * N + col]) = v;
        }
    }
}

// ---------------------------------------------------------------------------
// Flash attention: per block = one (b,h) and one 64-row Q tile.
// Iterates over 64-key tiles with online softmax. fp32 throughout.
// smem (dynamic): Qs[64][68] (d-major), Ks[64][68] (d-major),
//                 Vs[64][68] (key-major), Ps[64][68] (key-major, P^T)
// ---------------------------------------------------------------------------
#define APITCH 68
#define ATTN_SMEM_FLOATS (4 * 64 * APITCH)

__global__ __launch_bounds__(256)
void attn_kernel(const float* __restrict__ gq, const float* __restrict__ gk,
                 const float* __restrict__ gv, const int* __restrict__ mask,
                 float* __restrict__ gctx)
{
    extern __shared__ float smdyn[];
    float* Qs = smdyn;                  // Qs[d*68 + r]
    float* Ks = Qs + 64 * APITCH;       // Ks[d*68 + c]
    float* Vs = Ks + 64 * APITCH;       // Vs[kk*68 + c]
    float* Ps = Vs + 64 * APITCH;       // Ps[kk*68 + r]
    __shared__ float mok[64];           // multiplicative mask per key

    const int tid = threadIdx.x;
    const int tx  = tid & 15;           // key-col / dh-col group
    const int ty  = tid >> 4;           // q-row group
    const int qt  = blockIdx.x * 64;
    const int bh  = blockIdx.y;
    const int b   = bh / NH;
    const int h   = bh % NH;
    const size_t headoff = (size_t)h * DH;

    // Load Q tile transposed (d-major) with 1/sqrt(DH) folded in
#pragma unroll
    for (int it = 0; it < 4; ++it) {
        int f   = it * 256 + tid;
        int row = f >> 4;               // 0..63
        int dq  = f & 15;               // 0..15
        float4 v = *reinterpret_cast<const float4*>(
            &gq[(size_t)(b * SEQ + qt + row) * DIMM + headoff + dq * 4]);
        Qs[(dq*4+0)*APITCH + row] = v.x * 0.125f;
        Qs[(dq*4+1)*APITCH + row] = v.y * 0.125f;
        Qs[(dq*4+2)*APITCH + row] = v.z * 0.125f;
        Qs[(dq*4+3)*APITCH + row] = v.w * 0.125f;
    }

    float m[4], l[4], o[4][4];
#pragma unroll
    for (int i = 0; i < 4; i++) {
        m[i] = -1e30f; l[i] = 0.f;
#pragma unroll
        for (int j = 0; j < 4; j++) o[i][j] = 0.f;
    }

    for (int kt = 0; kt < SEQ / 64; ++kt) {
        const int kbase = kt * 64;
        __syncthreads();   // prior iteration finished reading Ks/Vs/Ps

        // Load K (transposed) and V (natural) tiles
#pragma unroll
        for (int it = 0; it < 4; ++it) {
            int f   = it * 256 + tid;
            int row = f >> 4;
            int dq  = f & 15;
            size_t gofs = (size_t)(b * SEQ + kbase + row) * DIMM + headoff + dq * 4;
            float4 kv = *reinterpret_cast<const float4*>(&gk[gofs]);
            Ks[(dq*4+0)*APITCH + row] = kv.x;
            Ks[(dq*4+1)*APITCH + row] = kv.y;
            Ks[(dq*4+2)*APITCH + row] = kv.z;
            Ks[(dq*4+3)*APITCH + row] = kv.w;
            float4 vv = *reinterpret_cast<const float4*>(&gv[gofs]);
            *reinterpret_cast<float4*>(&Vs[row * APITCH + dq * 4]) = vv;
        }
        if (tid < 64)
            mok[tid] = (mask[b * SEQ + kbase + tid] != 0) ? 1.f : 0.f;
        __syncthreads();

        // S = Q @ K^T  (4x4 microtile per thread)
        float s[4][4];
#pragma unroll
        for (int i = 0; i < 4; i++)
#pragma unroll
            for (int j = 0; j < 4; j++) s[i][j] = 0.f;

#pragma unroll 8
        for (int d = 0; d < 64; ++d) {
            float4 qa = *reinterpret_cast<const float4*>(&Qs[d * APITCH + ty * 4]);
            float4 kb = *reinterpret_cast<const float4*>(&Ks[d * APITCH + tx * 4]);
            float a[4]  = {qa.x, qa.y, qa.z, qa.w};
            float bb[4] = {kb.x, kb.y, kb.z, kb.w};
#pragma unroll
            for (int i = 0; i < 4; i++)
#pragma unroll
                for (int j = 0; j < 4; j++)
                    s[i][j] = fmaf(a[i], bb[j], s[i][j]);
        }

        float mj[4];
#pragma unroll
        for (int j = 0; j < 4; j++) mj[j] = mok[tx * 4 + j];

        // Online softmax update (row groups of 16 lanes within half-warps)
#pragma unroll
        for (int i = 0; i < 4; i++) {
            float tm = -1e30f;
#pragma unroll
            for (int j = 0; j < 4; j++)
                tm = fmaxf(tm, mj[j] > 0.f ? s[i][j] : -1e30f);
#pragma unroll
            for (int off = 8; off >= 1; off >>= 1)
                tm = fmaxf(tm, __shfl_xor_sync(0xffffffffu, tm, off));
            float mnew  = fmaxf(m[i], tm);
            float alpha = __expf(m[i] - mnew);
            float rs = 0.f;
#pragma unroll
            for (int j = 0; j < 4; j++) {
                float p = __expf(fminf(s[i][j] - mnew, 80.f)) * mj[j];
                s[i][j] = p;
                rs += p;
            }
#pragma unroll
            for (int off = 8; off >= 1; off >>= 1)
                rs += __shfl_xor_sync(0xffffffffu, rs, off);
            l[i] = l[i] * alpha + rs;
            m[i] = mnew;
#pragma unroll
            for (int j = 0; j < 4; j++) o[i][j] *= alpha;
        }

        // Stage P transposed
#pragma unroll
        for (int i = 0; i < 4; i++)
#pragma unroll
            for (int j = 0; j < 4; j++)
                Ps[(tx*4+j) * APITCH + ty*4 + i] = s[i][j];
        __syncthreads();

        // O += P @ V
#pragma unroll 8
        for (int kk = 0; kk < 64; ++kk) {
            float4 pa = *reinterpret_cast<const float4*>(&Ps[kk * APITCH + ty * 4]);
            float4 vb = *reinterpret_cast<const float4*>(&Vs[kk * APITCH + tx * 4]);
            float p[4]  = {pa.x, pa.y, pa.z, pa.w};
            float vv[4] = {vb.x, vb.y, vb.z, vb.w};
#pragma unroll
            for (int i = 0; i < 4; i++)
#pragma unroll
                for (int j = 0; j < 4; j++)
                    o[i][j] = fmaf(p[i], vv[j], o[i][j]);
        }
    }

    // Normalize and write context (bs, q, h*dh)
#pragma unroll
    for (int i = 0; i < 4; i++) {
        float inv = 1.f / l[i];
        float4 v;
        v.x = o[i][0] * inv; v.y = o[i][1] * inv;
        v.z = o[i][2] * inv; v.w = o[i][3] * inv;
        *reinterpret_cast<float4*>(
            &gctx[(size_t)(b * SEQ + qt + ty * 4 + i) * DIMM + headoff + tx * 4]) = v;
    }
}

// ---------------------------------------------------------------------------
extern "C" void kernel_launch(void* const* d_in, const int* in_sizes, int n_in,
                              void* d_out, int out_size)
{
    const float* query = (const float*)d_in[0];
    const float* key_t = (const float*)d_in[1];
    const float* value = (const float*)d_in[2];
    const int*   mask  = (const int*)  d_in[3];
    const float* q_w   = (const float*)d_in[4];
    const float* q_b   = (const float*)d_in[5];
    const float* k_w   = (const float*)d_in[6];
    const float* k_b   = (const float*)d_in[7];
    const float* v_w   = (const float*)d_in[8];
    const float* v_b   = (const float*)d_in[9];
    const float* o_w   = (const float*)d_in[10];
    const float* o_b   = (const float*)d_in[11];
    float* out = (float*)d_out;

    float *gq, *gk, *gv, *gctx;
    cudaGetSymbolAddress((void**)&gq,   g_q);
    cudaGetSymbolAddress((void**)&gk,   g_k);
    cudaGetSymbolAddress((void**)&gv,   g_v);
    cudaGetSymbolAddress((void**)&gctx, g_ctx);

    const int attn_smem = ATTN_SMEM_FLOATS * (int)sizeof(float);  // 69632 B
    cudaFuncSetAttribute(attn_kernel,
                         cudaFuncAttributeMaxDynamicSharedMemorySize, attn_smem);

    dim3 gg(DIMM / GBN, NTOK / GBM);   // (6, 64)

    gemm_nt_bias<<<gg, 256>>>(query, q_w, q_b, gq, NTOK, DIMM, DIMM);
    gemm_nt_bias<<<gg, 256>>>(key_t, k_w, k_b, gk, NTOK, DIMM, DIMM);
    gemm_nt_bias<<<gg, 256>>>(value, v_w, v_b, gv, NTOK, DIMM, DIMM);

    attn_kernel<<<dim3(SEQ / 64, BSZ * NH), 256, attn_smem>>>(gq, gk, gv, mask, gctx);

    gemm_nt_bias<<<gg, 256>>>(gctx, o_w, o_b, out, NTOK, DIMM, DIMM);
}

// round 3
// speedup vs baseline: 1.2514x; 1.2514x over previous
#include <cuda_runtime.h>
#include <cuda_bf16.h>
#include <math.h>
#include <cstdint>

#define BSZ  4
#define SEQ  2048
#define DIMM 768
#define NH   12
#define DH   64
#define NTOK (BSZ*SEQ)   // 8192
#define KB3  (3*DIMM)    // 2304: A'=[hi,hi,lo], B'=[hi,lo,hi]

// ---------------- scratch (device globals; allocation is forbidden) --------
__device__ float g_q[(size_t)NTOK*DIMM];
__device__ float g_k[(size_t)NTOK*DIMM];
__device__ float g_v[(size_t)NTOK*DIMM];
__device__ float g_ctx[(size_t)NTOK*DIMM];
__device__ __align__(256) __nv_bfloat16 g_abuf[(size_t)NTOK*KB3];
__device__ __align__(256) __nv_bfloat16 g_wbuf[(size_t)DIMM*KB3];

// ---------------- helpers ---------------------------------------------------
__device__ __forceinline__ uint32_t smem_u32(const void* p) {
    uint32_t a;
    asm("{ .reg .u64 t; cvta.to.shared.u64 t, %1; cvt.u32.u64 %0, t; }" : "=r"(a) : "l"(p));
    return a;
}
__device__ __forceinline__ void ldsm_x4(uint32_t* r, uint32_t addr) {
    asm volatile("ldmatrix.sync.aligned.m8n8.x4.shared.b16 {%0,%1,%2,%3}, [%4];"
                 : "=r"(r[0]), "=r"(r[1]), "=r"(r[2]), "=r"(r[3]) : "r"(addr));
}
__device__ __forceinline__ void ldsm_x2(uint32_t* r, uint32_t addr) {
    asm volatile("ldmatrix.sync.aligned.m8n8.x2.shared.b16 {%0,%1}, [%2];"
                 : "=r"(r[0]), "=r"(r[1]) : "r"(addr));
}
__device__ __forceinline__ void mma_bf16(float* d, const uint32_t* a, const uint32_t* b) {
    asm volatile(
        "mma.sync.aligned.m16n8k16.row.col.f32.bf16.bf16.f32 "
        "{%0,%1,%2,%3}, {%4,%5,%6,%7}, {%8,%9}, {%0,%1,%2,%3};"
        : "+f"(d[0]), "+f"(d[1]), "+f"(d[2]), "+f"(d[3])
        : "r"(a[0]), "r"(a[1]), "r"(a[2]), "r"(a[3]), "r"(b[0]), "r"(b[1]));
}

// ---------------------------------------------------------------------------
// fp32 -> bf16 3-way split. mode 0 (activations): [hi, hi, lo]
//                           mode 1 (weights):     [hi, lo, hi]
// ---------------------------------------------------------------------------
__global__ void split_bf16(const float* __restrict__ X, __nv_bfloat16* __restrict__ Y,
                           int nquads, int mode)
{
    int i = blockIdx.x * blockDim.x + threadIdx.x;
    if (i >= nquads) return;
    int r = i / 192;
    int k = (i % 192) * 4;
    float4 v = *reinterpret_cast<const float4*>(&X[(size_t)r * DIMM + k]);
    float a[4] = {v.x, v.y, v.z, v.w};
    __nv_bfloat16 h[4], l[4];
#pragma unroll
    for (int e = 0; e < 4; e++) {
        h[e] = __float2bfloat16_rn(a[e]);
        l[e] = __float2bfloat16_rn(a[e] - __bfloat162float(h[e]));
    }
    uint2 hh, ll;
    {
        __nv_bfloat162 p0(h[0], h[1]), p1(h[2], h[3]);
        hh.x = *reinterpret_cast<uint32_t*>(&p0); hh.y = *reinterpret_cast<uint32_t*>(&p1);
        __nv_bfloat162 q0(l[0], l[1]), q1(l[2], l[3]);
        ll.x = *reinterpret_cast<uint32_t*>(&q0); ll.y = *reinterpret_cast<uint32_t*>(&q1);
    }
    size_t ro = (size_t)r * KB3;
    *reinterpret_cast<uint2*>(&Y[ro + k])            = hh;
    *reinterpret_cast<uint2*>(&Y[ro + DIMM + k])     = mode ? ll : hh;
    *reinterpret_cast<uint2*>(&Y[ro + 2 * DIMM + k]) = mode ? hh : ll;
}

// ---------------------------------------------------------------------------
// HMMA GEMM: C[M,768] = A'[M,2304](bf16) @ B'[768,2304]^T(bf16) + bias
// 128x128 block tile, BK=32, 8 warps (2m x 4n), warp tile 64x32.
// smem pitch 80 B/row -> conflict-free ldmatrix. Double buffered.
// ---------------------------------------------------------------------------
#define NST (KB3/32)   // 72

__global__ __launch_bounds__(256, 2)
void gemm_hmma(const __nv_bfloat16* __restrict__ A, const __nv_bfloat16* __restrict__ B,
               const float* __restrict__ bias, float* __restrict__ C)
{
    __shared__ __align__(16) unsigned char smA[2][128 * 80];
    __shared__ __align__(16) unsigned char smB[2][128 * 80];

    const int tid    = threadIdx.x;
    const int lane   = tid & 31;
    const int wid    = tid >> 5;
    const int warp_m = wid & 1;     // 0..1 -> 64 rows
    const int warp_n = wid >> 1;    // 0..3 -> 32 cols
    const int bm = blockIdx.y * 128;
    const int bn = blockIdx.x * 128;

    const int lc  = tid & 3;        // 16B chunk within 64B k-slab
    const int lr0 = tid >> 2;       // 0..63

    float acc[4][4][4];
#pragma unroll
    for (int i = 0; i < 4; i++)
#pragma unroll
        for (int j = 0; j < 4; j++)
#pragma unroll
            for (int e = 0; e < 4; e++) acc[i][j][e] = 0.f;

    uint4 pa[2], pb[2];
    auto ldg = [&](int s) {
        const size_t ke = (size_t)s * 32 + lc * 8;
#pragma unroll
        for (int p = 0; p < 2; p++) {
            int r = lr0 + 64 * p;
            pa[p] = *reinterpret_cast<const uint4*>(&A[(size_t)(bm + r) * KB3 + ke]);
            pb[p] = *reinterpret_cast<const uint4*>(&B[(size_t)(bn + r) * KB3 + ke]);
        }
    };
    auto sts = [&](int buf) {
#pragma unroll
        for (int p = 0; p < 2; p++) {
            int r = lr0 + 64 * p;
            *reinterpret_cast<uint4*>(&smA[buf][r * 80 + lc * 16]) = pa[p];
            *reinterpret_cast<uint4*>(&smB[buf][r * 80 + lc * 16]) = pb[p];
        }
    };

    ldg(0);
    sts(0);
    __syncthreads();

    for (int s = 0; s < NST; s++) {
        const int buf = s & 1;
        if (s + 1 < NST) ldg(s + 1);

#pragma unroll
        for (int kk = 0; kk < 2; kk++) {
            uint32_t af[4][4], bf[4][2];
            const int achk = kk * 2 + (lane >> 4);          // 0..3
            const int arow0 = warp_m * 64 + (lane & 15);
#pragma unroll
            for (int mt = 0; mt < 4; mt++)
                ldsm_x4(af[mt], smem_u32(&smA[buf][(arow0 + mt * 16) * 80 + achk * 16]));
            const int bchk = kk * 2 + ((lane >> 3) & 1);    // lanes 0-15 meaningful
            const int brow0 = warp_n * 32 + (lane & 7);
#pragma unroll
            for (int nt = 0; nt < 4; nt++)
                ldsm_x2(bf[nt], smem_u32(&smB[buf][(brow0 + nt * 8) * 80 + bchk * 16]));
#pragma unroll
            for (int mt = 0; mt < 4; mt++)
#pragma unroll
                for (int nt = 0; nt < 4; nt++)
                    mma_bf16(acc[mt][nt], af[mt], bf[nt]);
        }
        __syncthreads();
        if (s + 1 < NST) {
            sts(buf ^ 1);
            __syncthreads();
        }
    }

    // ---- epilogue: add bias, store (float2 per c-pair) ----
    const int rbase = bm + warp_m * 64 + (lane >> 2);
    const int cbase = bn + warp_n * 32 + (lane & 3) * 2;
#pragma unroll
    for (int mt = 0; mt < 4; mt++) {
#pragma unroll
        for (int nt = 0; nt < 4; nt++) {
            const int col = cbase + nt * 8;
            const float b0 = bias[col], b1 = bias[col + 1];
            float2 v0 = {acc[mt][nt][0] + b0, acc[mt][nt][1] + b1};
            float2 v1 = {acc[mt][nt][2] + b0, acc[mt][nt][3] + b1};
            const int r0 = rbase + mt * 16;
            *reinterpret_cast<float2*>(&C[(size_t)r0 * DIMM + col])       = v0;
            *reinterpret_cast<float2*>(&C[(size_t)(r0 + 8) * DIMM + col]) = v1;
        }
    }
}

// ---------------------------------------------------------------------------
// Flash attention (unchanged): fp32, 64x64 tiles, online softmax
// ---------------------------------------------------------------------------
#define APITCH 68
#define ATTN_SMEM_FLOATS (4 * 64 * APITCH)

__global__ __launch_bounds__(256)
void attn_kernel(const float* __restrict__ gq, const float* __restrict__ gk,
                 const float* __restrict__ gv, const int* __restrict__ mask,
                 float* __restrict__ gctx)
{
    extern __shared__ float smdyn[];
    float* Qs = smdyn;
    float* Ks = Qs + 64 * APITCH;
    float* Vs = Ks + 64 * APITCH;
    float* Ps = Vs + 64 * APITCH;
    __shared__ float mok[64];

    const int tid = threadIdx.x;
    const int tx  = tid & 15;
    const int ty  = tid >> 4;
    const int qt  = blockIdx.x * 64;
    const int bh  = blockIdx.y;
    const int b   = bh / NH;
    const int h   = bh % NH;
    const size_t headoff = (size_t)h * DH;

#pragma unroll
    for (int it = 0; it < 4; ++it) {
        int f   = it * 256 + tid;
        int row = f >> 4;
        int dq  = f & 15;
        float4 v = *reinterpret_cast<const float4*>(
            &gq[(size_t)(b * SEQ + qt + row) * DIMM + headoff + dq * 4]);
        Qs[(dq*4+0)*APITCH + row] = v.x * 0.125f;
        Qs[(dq*4+1)*APITCH + row] = v.y * 0.125f;
        Qs[(dq*4+2)*APITCH + row] = v.z * 0.125f;
        Qs[(dq*4+3)*APITCH + row] = v.w * 0.125f;
    }

    float m[4], l[4], o[4][4];
#pragma unroll
    for (int i = 0; i < 4; i++) {
        m[i] = -1e30f; l[i] = 0.f;
#pragma unroll
        for (int j = 0; j < 4; j++) o[i][j] = 0.f;
    }

    for (int kt = 0; kt < SEQ / 64; ++kt) {
        const int kbase = kt * 64;
        __syncthreads();
#pragma unroll
        for (int it = 0; it < 4; ++it) {
            int f   = it * 256 + tid;
            int row = f >> 4;
            int dq  = f & 15;
            size_t gofs = (size_t)(b * SEQ + kbase + row) * DIMM + headoff + dq * 4;
            float4 kv = *reinterpret_cast<const float4*>(&gk[gofs]);
            Ks[(dq*4+0)*APITCH + row] = kv.x;
            Ks[(dq*4+1)*APITCH + row] = kv.y;
            Ks[(dq*4+2)*APITCH + row] = kv.z;
            Ks[(dq*4+3)*APITCH + row] = kv.w;
            float4 vv = *reinterpret_cast<const float4*>(&gv[gofs]);
            *reinterpret_cast<float4*>(&Vs[row * APITCH + dq * 4]) = vv;
        }
        if (tid < 64)
            mok[tid] = (mask[b * SEQ + kbase + tid] != 0) ? 1.f : 0.f;
        __syncthreads();

        float s[4][4];
#pragma unroll
        for (int i = 0; i < 4; i++)
#pragma unroll
            for (int j = 0; j < 4; j++) s[i][j] = 0.f;

#pragma unroll 8
        for (int d = 0; d < 64; ++d) {
            float4 qa = *reinterpret_cast<const float4*>(&Qs[d * APITCH + ty * 4]);
            float4 kb = *reinterpret_cast<const float4*>(&Ks[d * APITCH + tx * 4]);
            float a[4]  = {qa.x, qa.y, qa.z, qa.w};
            float bb[4] = {kb.x, kb.y, kb.z, kb.w};
#pragma unroll
            for (int i = 0; i < 4; i++)
#pragma unroll
                for (int j = 0; j < 4; j++)
                    s[i][j] = fmaf(a[i], bb[j], s[i][j]);
        }

        float mj[4];
#pragma unroll
        for (int j = 0; j < 4; j++) mj[j] = mok[tx * 4 + j];

#pragma unroll
        for (int i = 0; i < 4; i++) {
            float tm = -1e30f;
#pragma unroll
            for (int j = 0; j < 4; j++)
                tm = fmaxf(tm, mj[j] > 0.f ? s[i][j] : -1e30f);
#pragma unroll
            for (int off = 8; off >= 1; off >>= 1)
                tm = fmaxf(tm, __shfl_xor_sync(0xffffffffu, tm, off));
            float mnew  = fmaxf(m[i], tm);
            float alpha = __expf(m[i] - mnew);
            float rs = 0.f;
#pragma unroll
            for (int j = 0; j < 4; j++) {
                float p = __expf(fminf(s[i][j] - mnew, 80.f)) * mj[j];
                s[i][j] = p;
                rs += p;
            }
#pragma unroll
            for (int off = 8; off >= 1; off >>= 1)
                rs += __shfl_xor_sync(0xffffffffu, rs, off);
            l[i] = l[i] * alpha + rs;
            m[i] = mnew;
#pragma unroll
            for (int j = 0; j < 4; j++) o[i][j] *= alpha;
        }

#pragma unroll
        for (int i = 0; i < 4; i++)
#pragma unroll
            for (int j = 0; j < 4; j++)
                Ps[(tx*4+j) * APITCH + ty*4 + i] = s[i][j];
        __syncthreads();

#pragma unroll 8
        for (int kk = 0; kk < 64; ++kk) {
            float4 pa = *reinterpret_cast<const float4*>(&Ps[kk * APITCH + ty * 4]);
            float4 vb = *reinterpret_cast<const float4*>(&Vs[kk * APITCH + tx * 4]);
            float p[4]  = {pa.x, pa.y, pa.z, pa.w};
            float vv[4] = {vb.x, vb.y, vb.z, vb.w};
#pragma unroll
            for (int i = 0; i < 4; i++)
#pragma unroll
                for (int j = 0; j < 4; j++)
                    o[i][j] = fmaf(p[i], vv[j], o[i][j]);
        }
    }

#pragma unroll
    for (int i = 0; i < 4; i++) {
        float inv = 1.f / l[i];
        float4 v;
        v.x = o[i][0] * inv; v.y = o[i][1] * inv;
        v.z = o[i][2] * inv; v.w = o[i][3] * inv;
        *reinterpret_cast<float4*>(
            &gctx[(size_t)(b * SEQ + qt + ty * 4 + i) * DIMM + headoff + tx * 4]) = v;
    }
}

// ---------------------------------------------------------------------------
extern "C" void kernel_launch(void* const* d_in, const int* in_sizes, int n_in,
                              void* d_out, int out_size)
{
    const float* query = (const float*)d_in[0];
    const float* key_t = (const float*)d_in[1];
    const float* value = (const float*)d_in[2];
    const int*   mask  = (const int*)  d_in[3];
    const float* q_w   = (const float*)d_in[4];
    const float* q_b   = (const float*)d_in[5];
    const float* k_w   = (const float*)d_in[6];
    const float* k_b   = (const float*)d_in[7];
    const float* v_w   = (const float*)d_in[8];
    const float* v_b   = (const float*)d_in[9];
    const float* o_w   = (const float*)d_in[10];
    const float* o_b   = (const float*)d_in[11];
    float* out = (float*)d_out;

    float *gq, *gk, *gv, *gctx;
    __nv_bfloat16 *gab, *gwb;
    cudaGetSymbolAddress((void**)&gq,   g_q);
    cudaGetSymbolAddress((void**)&gk,   g_k);
    cudaGetSymbolAddress((void**)&gv,   g_v);
    cudaGetSymbolAddress((void**)&gctx, g_ctx);
    cudaGetSymbolAddress((void**)&gab,  g_abuf);
    cudaGetSymbolAddress((void**)&gwb,  g_wbuf);

    const int attn_smem = ATTN_SMEM_FLOATS * (int)sizeof(float);
    cudaFuncSetAttribute(attn_kernel,
                         cudaFuncAttributeMaxDynamicSharedMemorySize, attn_smem);

    const int actq = NTOK * 192, wq = DIMM * 192;
    const dim3 ggrid(DIMM / 128, NTOK / 128);   // (6, 64)

    split_bf16<<<(actq + 255) / 256, 256>>>(query, gab, actq, 0);
    split_bf16<<<(wq   + 255) / 256, 256>>>(q_w,   gwb, wq,   1);
    gemm_hmma<<<ggrid, 256>>>(gab, gwb, q_b, gq);

    split_bf16<<<(actq + 255) / 256, 256>>>(key_t, gab, actq, 0);
    split_bf16<<<(wq   + 255) / 256, 256>>>(k_w,   gwb, wq,   1);
    gemm_hmma<<<ggrid, 256>>>(gab, gwb, k_b, gk);

    split_bf16<<<(actq + 255) / 256, 256>>>(value, gab, actq, 0);
    split_bf16<<<(wq   + 255) / 256, 256>>>(v_w,   gwb, wq,   1);
    gemm_hmma<<<ggrid, 256>>>(gab, gwb, v_b, gv);

    attn_kernel<<<dim3(SEQ / 64, BSZ * NH), 256, attn_smem>>>(gq, gk, gv, mask, gctx);

    split_bf16<<<(actq + 255) / 256, 256>>>(gctx, gab, actq, 0);
    split_bf16<<<(wq   + 255) / 256, 256>>>(o_w,  gwb, wq,   1);
    gemm_hmma<<<ggrid, 256>>>(gab, gwb, o_b, out);
}

// round 4
// speedup vs baseline: 2.5580x; 2.0441x over previous
#include <cuda_runtime.h>
#include <cuda_bf16.h>
#include <math.h>
#include <cstdint>

#define BSZ  4
#define SEQ  2048
#define DIMM 768
#define NH   12
#define DH   64
#define NTOK (BSZ*SEQ)   // 8192
#define KB3  (3*DIMM)    // 2304
#define KE   192         // split head dim: [hi64, hi64/lo64, lo64/hi64]

// ---------------- scratch (device globals) ----------------------------------
__device__ __align__(256) __nv_bfloat16 g_abuf[(size_t)NTOK*KB3];
__device__ __align__(256) __nv_bfloat16 g_wbuf[(size_t)DIMM*KB3];
__device__ __align__(256) __nv_bfloat16 g_qe [(size_t)BSZ*NH*SEQ*KE];
__device__ __align__(256) __nv_bfloat16 g_ke [(size_t)BSZ*NH*SEQ*KE];
__device__ __align__(256) __nv_bfloat16 g_vth[(size_t)BSZ*NH*DH*SEQ];
__device__ __align__(256) __nv_bfloat16 g_vtl[(size_t)BSZ*NH*DH*SEQ];
__device__ __align__(256) __nv_bfloat16 g_ce [(size_t)NTOK*KB3];

// ---------------- helpers ---------------------------------------------------
__device__ __forceinline__ uint32_t smem_u32(const void* p) {
    uint32_t a;
    asm("{ .reg .u64 t; cvta.to.shared.u64 t, %1; cvt.u32.u64 %0, t; }" : "=r"(a) : "l"(p));
    return a;
}
__device__ __forceinline__ void ldsm_x4(uint32_t* r, uint32_t addr) {
    asm volatile("ldmatrix.sync.aligned.m8n8.x4.shared.b16 {%0,%1,%2,%3}, [%4];"
                 : "=r"(r[0]), "=r"(r[1]), "=r"(r[2]), "=r"(r[3]) : "r"(addr));
}
__device__ __forceinline__ void ldsm_x2(uint32_t* r, uint32_t addr) {
    asm volatile("ldmatrix.sync.aligned.m8n8.x2.shared.b16 {%0,%1}, [%2];"
                 : "=r"(r[0]), "=r"(r[1]) : "r"(addr));
}
__device__ __forceinline__ void mma_bf16(float* d, const uint32_t* a, const uint32_t* b) {
    asm volatile(
        "mma.sync.aligned.m16n8k16.row.col.f32.bf16.bf16.f32 "
        "{%0,%1,%2,%3}, {%4,%5,%6,%7}, {%8,%9}, {%0,%1,%2,%3};"
        : "+f"(d[0]), "+f"(d[1]), "+f"(d[2]), "+f"(d[3])
        : "r"(a[0]), "r"(a[1]), "r"(a[2]), "r"(a[3]), "r"(b[0]), "r"(b[1]));
}
__device__ __forceinline__ void cpa16(uint32_t dst, const void* src) {
    asm volatile("cp.async.cg.shared.global [%0], [%1], 16;" :: "r"(dst), "l"(src));
}
#define CPA_COMMIT() asm volatile("cp.async.commit_group;" ::: "memory")
#define CPA_WAIT1()  asm volatile("cp.async.wait_group 1;" ::: "memory")
#define CPA_WAIT0()  asm volatile("cp.async.wait_group 0;" ::: "memory")

__device__ __forceinline__ uint32_t packbf(float a, float b) {
    __nv_bfloat162 t(__float2bfloat16_rn(a), __float2bfloat16_rn(b));
    return *reinterpret_cast<uint32_t*>(&t);
}

// ---------------------------------------------------------------------------
// fp32 -> bf16 3-way split for GEMM inputs.
// mode 0 (activations): [hi, hi, lo]; mode 1 (weights): [hi, lo, hi]
// ---------------------------------------------------------------------------
__global__ void split_bf16(const float* __restrict__ X, __nv_bfloat16* __restrict__ Y,
                           int nquads, int mode)
{
    int i = blockIdx.x * blockDim.x + threadIdx.x;
    if (i >= nquads) return;
    int r = i / 192;
    int k = (i % 192) * 4;
    float4 v = *reinterpret_cast<const float4*>(&X[(size_t)r * DIMM + k]);
    float a[4] = {v.x, v.y, v.z, v.w};
    __nv_bfloat16 h[4], l[4];
#pragma unroll
    for (int e = 0; e < 4; e++) {
        h[e] = __float2bfloat16_rn(a[e]);
        l[e] = __float2bfloat16_rn(a[e] - __bfloat162float(h[e]));
    }
    uint2 hh, ll;
    {
        __nv_bfloat162 p0(h[0], h[1]), p1(h[2], h[3]);
        hh.x = *reinterpret_cast<uint32_t*>(&p0); hh.y = *reinterpret_cast<uint32_t*>(&p1);
        __nv_bfloat162 q0(l[0], l[1]), q1(l[2], l[3]);
        ll.x = *reinterpret_cast<uint32_t*>(&q0); ll.y = *reinterpret_cast<uint32_t*>(&q1);
    }
    size_t ro = (size_t)r * KB3;
    *reinterpret_cast<uint2*>(&Y[ro + k])            = hh;
    *reinterpret_cast<uint2*>(&Y[ro + DIMM + k])     = mode ? ll : hh;
    *reinterpret_cast<uint2*>(&Y[ro + 2 * DIMM + k]) = mode ? hh : ll;
}

// ---------------------------------------------------------------------------
// HMMA GEMM with fused epilogues.
// mode 0: C = fp32 + bias -> outf
// mode 1: Q: ((acc+bias)*0.125) split -> q_eff [Qh,Qh,Ql] per (bh,q)
// mode 2: K: (acc+bias) split -> k_eff [Kh,Kl,Kh]
// mode 3: V: (acc+bias) split -> vt_hi/vt_lo transposed [bh][d][seq]
// ---------------------------------------------------------------------------
#define NST (KB3/32)   // 72

__global__ __launch_bounds__(256, 2)
void gemm_hmma(const __nv_bfloat16* __restrict__ A, const __nv_bfloat16* __restrict__ B,
               const float* __restrict__ bias, int mode, float* __restrict__ outf,
               __nv_bfloat16* __restrict__ aux0, __nv_bfloat16* __restrict__ aux1)
{
    __shared__ __align__(16) unsigned char smA[2][128 * 80];
    __shared__ __align__(16) unsigned char smB[2][128 * 80];

    const int tid    = threadIdx.x;
    const int lane   = tid & 31;
    const int wid    = tid >> 5;
    const int warp_m = wid & 1;
    const int warp_n = wid >> 1;
    const int bm = blockIdx.y * 128;
    const int bn = blockIdx.x * 128;

    const int lc  = tid & 3;
    const int lr0 = tid >> 2;

    float acc[4][4][4];
#pragma unroll
    for (int i = 0; i < 4; i++)
#pragma unroll
        for (int j = 0; j < 4; j++)
#pragma unroll
            for (int e = 0; e < 4; e++) acc[i][j][e] = 0.f;

    uint4 pa[2], pb[2];
    auto ldg = [&](int s) {
        const size_t ke_ = (size_t)s * 32 + lc * 8;
#pragma unroll
        for (int p = 0; p < 2; p++) {
            int r = lr0 + 64 * p;
            pa[p] = *reinterpret_cast<const uint4*>(&A[(size_t)(bm + r) * KB3 + ke_]);
            pb[p] = *reinterpret_cast<const uint4*>(&B[(size_t)(bn + r) * KB3 + ke_]);
        }
    };
    auto sts = [&](int buf) {
#pragma unroll
        for (int p = 0; p < 2; p++) {
            int r = lr0 + 64 * p;
            *reinterpret_cast<uint4*>(&smA[buf][r * 80 + lc * 16]) = pa[p];
            *reinterpret_cast<uint4*>(&smB[buf][r * 80 + lc * 16]) = pb[p];
        }
    };

    ldg(0);
    sts(0);
    __syncthreads();

    for (int s = 0; s < NST; s++) {
        const int buf = s & 1;
        if (s + 1 < NST) ldg(s + 1);

#pragma unroll
        for (int kk = 0; kk < 2; kk++) {
            uint32_t af[4][4], bf[4][2];
            const int achk = kk * 2 + (lane >> 4);
            const int arow0 = warp_m * 64 + (lane & 15);
#pragma unroll
            for (int mt = 0; mt < 4; mt++)
                ldsm_x4(af[mt], smem_u32(&smA[buf][(arow0 + mt * 16) * 80 + achk * 16]));
            const int bchk = kk * 2 + ((lane >> 3) & 1);
            const int brow0 = warp_n * 32 + (lane & 7);
#pragma unroll
            for (int nt = 0; nt < 4; nt++)
                ldsm_x2(bf[nt], smem_u32(&smB[buf][(brow0 + nt * 8) * 80 + bchk * 16]));
#pragma unroll
            for (int mt = 0; mt < 4; mt++)
#pragma unroll
                for (int nt = 0; nt < 4; nt++)
                    mma_bf16(acc[mt][nt], af[mt], bf[nt]);
        }
        __syncthreads();
        if (s + 1 < NST) {
            sts(buf ^ 1);
            __syncthreads();
        }
    }

    // ---- epilogue ----
    const int rbase = bm + warp_m * 64 + (lane >> 2);
    const int cbase = bn + warp_n * 32 + (lane & 3) * 2;
#pragma unroll
    for (int mt = 0; mt < 4; mt++) {
#pragma unroll
        for (int nt = 0; nt < 4; nt++) {
            const int col = cbase + nt * 8;
            const float b0 = bias[col], b1 = bias[col + 1];
            const int r0 = rbase + mt * 16;
#pragma unroll
            for (int rh = 0; rh < 2; rh++) {
                const int row = r0 + rh * 8;
                float x0 = acc[mt][nt][rh * 2 + 0] + b0;
                float x1 = acc[mt][nt][rh * 2 + 1] + b1;
                if (mode == 0) {
                    float2 v = {x0, x1};
                    *reinterpret_cast<float2*>(&outf[(size_t)row * DIMM + col]) = v;
                } else {
                    const int b_  = row >> 11, pos = row & 2047;
                    const int h_  = col >> 6,  d   = col & 63;
                    if (mode == 1) { x0 *= 0.125f; x1 *= 0.125f; }
                    __nv_bfloat16 h0 = __float2bfloat16_rn(x0);
                    __nv_bfloat16 h1 = __float2bfloat16_rn(x1);
                    float l0f = x0 - __bfloat162float(h0);
                    float l1f = x1 - __bfloat162float(h1);
                    if (mode == 3) {
                        size_t base = ((size_t)(b_ * NH + h_) * DH + d) * SEQ + pos;
                        aux0[base]       = h0;
                        aux0[base + SEQ] = h1;
                        aux1[base]       = __float2bfloat16_rn(l0f);
                        aux1[base + SEQ] = __float2bfloat16_rn(l1f);
                    } else {
                        __nv_bfloat162 hhp(h0, h1);
                        uint32_t hh = *reinterpret_cast<uint32_t*>(&hhp);
                        uint32_t ll = packbf(l0f, l1f);
                        size_t base = ((size_t)(b_ * NH + h_) * SEQ + pos) * KE + d;
                        uint32_t* p = reinterpret_cast<uint32_t*>(aux0 + base);
                        p[0] = hh;
                        *reinterpret_cast<uint32_t*>(aux0 + base + 64)  = (mode == 1) ? hh : ll;
                        *reinterpret_cast<uint32_t*>(aux0 + base + 128) = (mode == 1) ? ll : hh;
                    }
                }
            }
        }
    }
}

// ---------------------------------------------------------------------------
// HMMA flash attention.
// Block: 256 q rows x one (b,h). 8 warps x 32 rows. 64-key tiles, 32 tiles.
// QK: K-dim = 192 (3-term split). PV: 3 mma passes (Ph*Vh + Ph*Vl + Pl*Vh).
// ---------------------------------------------------------------------------
#define BR 256
#define BK 64
#define QP 400      // smem pitch bytes for 192-bf16 rows
#define VP 144      // smem pitch bytes for 64-bf16 rows
#define QS_OFF 0
#define KS_OFF 102400
#define KBUF   25600
#define VH_OFF 153600
#define VBUF   9216
#define VL_OFF 172032
#define MS_OFF 190464
#define ATT_SMEM 190976

__global__ __launch_bounds__(256)
void attn_hmma(const __nv_bfloat16* __restrict__ qe, const __nv_bfloat16* __restrict__ ke,
               const __nv_bfloat16* __restrict__ vth, const __nv_bfloat16* __restrict__ vtl,
               const int* __restrict__ mask, __nv_bfloat16* __restrict__ ctx)
{
    extern __shared__ unsigned char sm[];
    const uint32_t smb = smem_u32(sm);
    const int tid  = threadIdx.x;
    const int lane = tid & 31;
    const int wid  = tid >> 5;
    const int q0   = blockIdx.x * BR;
    const int bh   = blockIdx.y;
    const int b    = bh / NH;
    const int h    = bh - b * NH;

    // ---- async load of Q (whole block) ----
    const __nv_bfloat16* qg = qe + ((size_t)bh * SEQ + q0) * KE;
    for (int idx = tid; idx < BR * 24; idx += 256) {
        int row = idx / 24, ch = idx - row * 24;
        cpa16(smb + QS_OFF + row * QP + ch * 16,
              reinterpret_cast<const char*>(qg + (size_t)row * KE) + ch * 16);
    }

    auto load_tile = [&](int kt, int buf) {
        const int k0 = kt * BK;
        const __nv_bfloat16* kg = ke + ((size_t)bh * SEQ + k0) * KE;
        for (int idx = tid; idx < 64 * 24; idx += 256) {
            int r = idx / 24, ch = idx - r * 24;
            cpa16(smb + KS_OFF + buf * KBUF + r * QP + ch * 16,
                  reinterpret_cast<const char*>(kg + (size_t)r * KE) + ch * 16);
        }
        const size_t vg = (size_t)bh * DH * SEQ + k0;
        for (int idx = tid; idx < 64 * 8; idx += 256) {
            int d = idx >> 3, ch = idx & 7;
            cpa16(smb + VH_OFF + buf * VBUF + d * VP + ch * 16,
                  reinterpret_cast<const char*>(vth + vg + (size_t)d * SEQ) + ch * 16);
            cpa16(smb + VL_OFF + buf * VBUF + d * VP + ch * 16,
                  reinterpret_cast<const char*>(vtl + vg + (size_t)d * SEQ) + ch * 16);
        }
        if (tid < 16)
            cpa16(smb + MS_OFF + buf * 256 + tid * 16,
                  reinterpret_cast<const char*>(mask + (size_t)b * SEQ + k0) + tid * 16);
    };

    load_tile(0, 0);
    CPA_COMMIT();

    // ---- per-lane state ----
    float oacc[2][8][4];
    float m_[2][2], l_[2][2];
#pragma unroll
    for (int i = 0; i < 2; i++)
#pragma unroll
        for (int j = 0; j < 8; j++)
#pragma unroll
            for (int e = 0; e < 4; e++) oacc[i][j][e] = 0.f;
#pragma unroll
    for (int i = 0; i < 2; i++) { m_[i][0] = -1e30f; m_[i][1] = -1e30f; l_[i][0] = 0.f; l_[i][1] = 0.f; }

    // ldsm address components
    const int l8  = lane & 7;
    const int ms1 = (lane >> 3) & 1;   // +8 rows
    const int ms2 = (lane >> 4) & 1;   // +16B cols
    const uint32_t qrowadr = smb + QS_OFF + (wid * 32 + l8 + ms1 * 8) * QP + ms2 * 16;
    const uint32_t krowadr0 = smb + KS_OFF + (l8 + ms1 * 8) * QP + ms2 * 16;
    const int l16 = lane & 15;
    const uint32_t vrowadr0h = smb + VH_OFF + (l16 & 7) * VP + ((l16 >> 3) * 16);
    const uint32_t vrowadr0l = smb + VL_OFF + (l16 & 7) * VP + ((l16 >> 3) * 16);
    const int qc = (lane & 3) * 2;
    const int* Msm = reinterpret_cast<const int*>(sm + MS_OFF);

    for (int kt = 0; kt < SEQ / BK; kt++) {
        const int buf = kt & 1;
        if (kt + 1 < SEQ / BK) {
            load_tile(kt + 1, buf ^ 1);
            CPA_COMMIT();
            CPA_WAIT1();
        } else {
            CPA_WAIT0();
        }
        __syncthreads();

        // ---- S = Qeff @ Keff^T ----
        float sacc[2][8][4];
#pragma unroll
        for (int i = 0; i < 2; i++)
#pragma unroll
            for (int j = 0; j < 8; j++)
#pragma unroll
                for (int e = 0; e < 4; e++) sacc[i][j][e] = 0.f;

#pragma unroll
        for (int ks = 0; ks < KE / 16; ks++) {
            uint32_t af[2][4], bf[8][2];
#pragma unroll
            for (int mi = 0; mi < 2; mi++)
                ldsm_x4(af[mi], qrowadr + mi * (16 * QP) + ks * 32);
#pragma unroll
            for (int j = 0; j < 4; j++) {
                uint32_t t4[4];
                ldsm_x4(t4, krowadr0 + buf * KBUF + j * (16 * QP) + ks * 32);
                bf[2 * j][0] = t4[0]; bf[2 * j][1] = t4[2];
                bf[2 * j + 1][0] = t4[1]; bf[2 * j + 1][1] = t4[3];
            }
#pragma unroll
            for (int n = 0; n < 8; n++)
#pragma unroll
                for (int mi = 0; mi < 2; mi++)
                    mma_bf16(sacc[mi][n], af[mi], bf[n]);
        }

        // ---- mask + online softmax ----
        const int mbase = buf * 64 + qc;
#pragma unroll
        for (int mi = 0; mi < 2; mi++) {
#pragma unroll
            for (int rh = 0; rh < 2; rh++) {
                float mx = -1e30f;
#pragma unroll
                for (int j = 0; j < 8; j++) {
#pragma unroll
                    for (int c = 0; c < 1 + 1; c++) {
                        float v = sacc[mi][j][rh * 2 + c];
                        int mk = Msm[mbase + j * 8 + c];
                        v = mk ? v : -1e30f;
                        sacc[mi][j][rh * 2 + c] = v;
                        mx = fmaxf(mx, v);
                    }
                }
                mx = fmaxf(mx, __shfl_xor_sync(0xffffffffu, mx, 1));
                mx = fmaxf(mx, __shfl_xor_sync(0xffffffffu, mx, 2));
                const float mn = fmaxf(m_[mi][rh], mx);
                const float al = __expf(m_[mi][rh] - mn);
                float sum = 0.f;
#pragma unroll
                for (int j = 0; j < 8; j++) {
#pragma unroll
                    for (int c = 0; c < 2; c++) {
                        float p = __expf(sacc[mi][j][rh * 2 + c] - mn);
                        sacc[mi][j][rh * 2 + c] = p;
                        sum += p;
                    }
                }
                sum += __shfl_xor_sync(0xffffffffu, sum, 1);
                sum += __shfl_xor_sync(0xffffffffu, sum, 2);
                l_[mi][rh] = l_[mi][rh] * al + sum;
                m_[mi][rh] = mn;
#pragma unroll
                for (int j = 0; j < 8; j++) {
                    oacc[mi][j][rh * 2 + 0] *= al;
                    oacc[mi][j][rh * 2 + 1] *= al;
                }
            }
        }

        // ---- O += P @ V (3-term split) ----
#pragma unroll
        for (int t = 0; t < 4; t++) {
            uint32_t vhf[8][2], vlf[8][2];
#pragma unroll
            for (int n = 0; n < 8; n++) {
                ldsm_x2(vhf[n], vrowadr0h + buf * VBUF + n * (8 * VP) + t * 32);
                ldsm_x2(vlf[n], vrowadr0l + buf * VBUF + n * (8 * VP) + t * 32);
            }
#pragma unroll
            for (int mi = 0; mi < 2; mi++) {
                uint32_t ah[4], alr[4];
#pragma unroll
                for (int half = 0; half < 2; half++) {
                    const float* s4 = sacc[mi][2 * t + half];
#pragma unroll
                    for (int rh = 0; rh < 2; rh++) {
                        float p0 = s4[rh * 2 + 0], p1 = s4[rh * 2 + 1];
                        __nv_bfloat16 h0 = __float2bfloat16_rn(p0);
                        __nv_bfloat16 h1 = __float2bfloat16_rn(p1);
                        __nv_bfloat162 hp(h0, h1);
                        ah[half * 2 + rh]  = *reinterpret_cast<uint32_t*>(&hp);
                        alr[half * 2 + rh] = packbf(p0 - __bfloat162float(h0),
                                                    p1 - __bfloat162float(h1));
                    }
                }
                // a-frag order: a0=(r,k0) a1=(r+8,k0) a2=(r,k8) a3=(r+8,k8)
                uint32_t A_h[4] = {ah[0], ah[1], ah[2], ah[3]};
                uint32_t A_l[4] = {alr[0], alr[1], alr[2], alr[3]};
#pragma unroll
                for (int n = 0; n < 8; n++) {
                    mma_bf16(oacc[mi][n], A_h, vhf[n]);
                    mma_bf16(oacc[mi][n], A_h, vlf[n]);
                    mma_bf16(oacc[mi][n], A_l, vhf[n]);
                }
            }
        }
        __syncthreads();
    }

    // ---- finalize: O/l, split to ctx_eff [hi,hi,lo] ----
#pragma unroll
    for (int mi = 0; mi < 2; mi++) {
#pragma unroll
        for (int rh = 0; rh < 2; rh++) {
            const int row = wid * 32 + mi * 16 + rh * 8 + (lane >> 2);
            const float inv = 1.f / l_[mi][rh];
            const size_t tb = (size_t)(b * SEQ + q0 + row) * KB3 + h * 64 + qc;
#pragma unroll
            for (int j = 0; j < 8; j++) {
                float x0 = oacc[mi][j][rh * 2 + 0] * inv;
                float x1 = oacc[mi][j][rh * 2 + 1] * inv;
                __nv_bfloat16 h0 = __float2bfloat16_rn(x0);
                __nv_bfloat16 h1 = __float2bfloat16_rn(x1);
                __nv_bfloat162 hp(h0, h1);
                uint32_t hh = *reinterpret_cast<uint32_t*>(&hp);
                uint32_t ll = packbf(x0 - __bfloat162float(h0), x1 - __bfloat162float(h1));
                __nv_bfloat16* dst = ctx + tb + j * 8;
                *reinterpret_cast<uint32_t*>(dst)            = hh;
                *reinterpret_cast<uint32_t*>(dst + DIMM)     = hh;
                *reinterpret_cast<uint32_t*>(dst + 2 * DIMM) = ll;
            }
        }
    }
}

// ---------------------------------------------------------------------------
extern "C" void kernel_launch(void* const* d_in, const int* in_sizes, int n_in,
                              void* d_out, int out_size)
{
    const float* query = (const float*)d_in[0];
    const float* key_t = (const float*)d_in[1];
    const float* value = (const float*)d_in[2];
    const int*   mask  = (const int*)  d_in[3];
    const float* q_w   = (const float*)d_in[4];
    const float* q_b   = (const float*)d_in[5];
    const float* k_w   = (const float*)d_in[6];
    const float* k_b   = (const float*)d_in[7];
    const float* v_w   = (const float*)d_in[8];
    const float* v_b   = (const float*)d_in[9];
    const float* o_w   = (const float*)d_in[10];
    const float* o_b   = (const float*)d_in[11];
    float* out = (float*)d_out;

    __nv_bfloat16 *gab, *gwb, *gqe, *gke, *gvh, *gvl, *gce;
    cudaGetSymbolAddress((void**)&gab, g_abuf);
    cudaGetSymbolAddress((void**)&gwb, g_wbuf);
    cudaGetSymbolAddress((void**)&gqe, g_qe);
    cudaGetSymbolAddress((void**)&gke, g_ke);
    cudaGetSymbolAddress((void**)&gvh, g_vth);
    cudaGetSymbolAddress((void**)&gvl, g_vtl);
    cudaGetSymbolAddress((void**)&gce, g_ce);

    cudaFuncSetAttribute(attn_hmma,
                         cudaFuncAttributeMaxDynamicSharedMemorySize, ATT_SMEM);

    const int actq = NTOK * 192, wq = DIMM * 192;
    const dim3 ggrid(DIMM / 128, NTOK / 128);   // (6, 64)

    // Q projection -> q_eff (scaled + split)
    split_bf16<<<(actq + 255) / 256, 256>>>(query, gab, actq, 0);
    split_bf16<<<(wq   + 255) / 256, 256>>>(q_w,   gwb, wq,   1);
    gemm_hmma<<<ggrid, 256>>>(gab, gwb, q_b, 1, nullptr, gqe, nullptr);

    // K projection -> k_eff
    split_bf16<<<(actq + 255) / 256, 256>>>(key_t, gab, actq, 0);
    split_bf16<<<(wq   + 255) / 256, 256>>>(k_w,   gwb, wq,   1);
    gemm_hmma<<<ggrid, 256>>>(gab, gwb, k_b, 2, nullptr, gke, nullptr);

    // V projection -> vt_hi / vt_lo
    split_bf16<<<(actq + 255) / 256, 256>>>(value, gab, actq, 0);
    split_bf16<<<(wq   + 255) / 256, 256>>>(v_w,   gwb, wq,   1);
    gemm_hmma<<<ggrid, 256>>>(gab, gwb, v_b, 3, nullptr, gvh, gvl);

    // Attention -> ctx_eff (already split for the output projection)
    attn_hmma<<<dim3(SEQ / BR, BSZ * NH), 256, ATT_SMEM>>>(gqe, gke, gvh, gvl, mask, gce);

    // Output projection (fp32 out)
    split_bf16<<<(wq + 255) / 256, 256>>>(o_w, gwb, wq, 1);
    gemm_hmma<<<ggrid, 256>>>(gce, gwb, o_b, 0, out, nullptr, nullptr);
}

// round 5
// speedup vs baseline: 2.8008x; 1.0949x over previous
#include <cuda_runtime.h>
#include <cuda_bf16.h>
#include <math.h>
#include <cstdint>

#define BSZ  4
#define SEQ  2048
#define DIMM 768
#define NH   12
#define DH   64
#define NTOK (BSZ*SEQ)   // 8192
#define KB3  (3*DIMM)    // 2304
#define KE   192

// ---------------- scratch (device globals) ----------------------------------
__device__ __align__(256) __nv_bfloat16 g_a0 [(size_t)NTOK*KB3];
__device__ __align__(256) __nv_bfloat16 g_a1 [(size_t)NTOK*KB3];
__device__ __align__(256) __nv_bfloat16 g_a2 [(size_t)NTOK*KB3];
__device__ __align__(256) __nv_bfloat16 g_w0 [(size_t)DIMM*KB3];
__device__ __align__(256) __nv_bfloat16 g_w1 [(size_t)DIMM*KB3];
__device__ __align__(256) __nv_bfloat16 g_w2 [(size_t)DIMM*KB3];
__device__ __align__(256) __nv_bfloat16 g_w3 [(size_t)DIMM*KB3];
__device__ __align__(256) __nv_bfloat16 g_qe [(size_t)BSZ*NH*SEQ*KE];
__device__ __align__(256) __nv_bfloat16 g_ke [(size_t)BSZ*NH*SEQ*KE];
__device__ __align__(256) __nv_bfloat16 g_vth[(size_t)BSZ*NH*DH*SEQ];
__device__ __align__(256) __nv_bfloat16 g_vtl[(size_t)BSZ*NH*DH*SEQ];
__device__ __align__(256) __nv_bfloat16 g_ce [(size_t)NTOK*KB3];

// ---------------- helpers ---------------------------------------------------
__device__ __forceinline__ uint32_t smem_u32(const void* p) {
    uint32_t a;
    asm("{ .reg .u64 t; cvta.to.shared.u64 t, %1; cvt.u32.u64 %0, t; }" : "=r"(a) : "l"(p));
    return a;
}
__device__ __forceinline__ void ldsm_x4(uint32_t* r, uint32_t addr) {
    asm volatile("ldmatrix.sync.aligned.m8n8.x4.shared.b16 {%0,%1,%2,%3}, [%4];"
                 : "=r"(r[0]), "=r"(r[1]), "=r"(r[2]), "=r"(r[3]) : "r"(addr));
}
__device__ __forceinline__ void ldsm_x2(uint32_t* r, uint32_t addr) {
    asm volatile("ldmatrix.sync.aligned.m8n8.x2.shared.b16 {%0,%1}, [%2];"
                 : "=r"(r[0]), "=r"(r[1]) : "r"(addr));
}
__device__ __forceinline__ void mma_bf16(float* d, const uint32_t* a, const uint32_t* b) {
    asm volatile(
        "mma.sync.aligned.m16n8k16.row.col.f32.bf16.bf16.f32 "
        "{%0,%1,%2,%3}, {%4,%5,%6,%7}, {%8,%9}, {%0,%1,%2,%3};"
        : "+f"(d[0]), "+f"(d[1]), "+f"(d[2]), "+f"(d[3])
        : "r"(a[0]), "r"(a[1]), "r"(a[2]), "r"(a[3]), "r"(b[0]), "r"(b[1]));
}
__device__ __forceinline__ void cpa16(uint32_t dst, const void* src) {
    asm volatile("cp.async.cg.shared.global [%0], [%1], 16;" :: "r"(dst), "l"(src));
}
#define CPA_COMMIT() asm volatile("cp.async.commit_group;" ::: "memory")
#define CPA_WAIT1()  asm volatile("cp.async.wait_group 1;" ::: "memory")
#define CPA_WAIT0()  asm volatile("cp.async.wait_group 0;" ::: "memory")

__device__ __forceinline__ uint32_t packbf(float a, float b) {
    __nv_bfloat162 t(__float2bfloat16_rn(a), __float2bfloat16_rn(b));
    return *reinterpret_cast<uint32_t*>(&t);
}

// ---------------------------------------------------------------------------
// Fused split: all 7 tensors in one launch. blockIdx.y picks the job.
// jobs 0-2: activations (query/key_t/value), mode 0 [hi,hi,lo], 8192 rows
// jobs 3-6: weights (q/k/v/o), mode 1 [hi,lo,hi], 768 rows
// ---------------------------------------------------------------------------
__global__ void split_all(const float* __restrict__ q, const float* __restrict__ kt,
                          const float* __restrict__ v,
                          const float* __restrict__ qw, const float* __restrict__ kw,
                          const float* __restrict__ vw, const float* __restrict__ ow,
                          __nv_bfloat16* __restrict__ a0, __nv_bfloat16* __restrict__ a1,
                          __nv_bfloat16* __restrict__ a2, __nv_bfloat16* __restrict__ w0,
                          __nv_bfloat16* __restrict__ w1, __nv_bfloat16* __restrict__ w2,
                          __nv_bfloat16* __restrict__ w3)
{
    const int job = blockIdx.y;
    const float* X; __nv_bfloat16* Y; int rows, mode;
    switch (job) {
        case 0: X = q;  Y = a0; rows = NTOK; mode = 0; break;
        case 1: X = kt; Y = a1; rows = NTOK; mode = 0; break;
        case 2: X = v;  Y = a2; rows = NTOK; mode = 0; break;
        case 3: X = qw; Y = w0; rows = DIMM; mode = 1; break;
        case 4: X = kw; Y = w1; rows = DIMM; mode = 1; break;
        case 5: X = vw; Y = w2; rows = DIMM; mode = 1; break;
        default: X = ow; Y = w3; rows = DIMM; mode = 1; break;
    }
    const int nquads = rows * 192;
    int i = blockIdx.x * blockDim.x + threadIdx.x;
    if (i >= nquads) return;
    int r = i / 192;
    int k = (i % 192) * 4;
    float4 vv = *reinterpret_cast<const float4*>(&X[(size_t)r * DIMM + k]);
    float a[4] = {vv.x, vv.y, vv.z, vv.w};
    __nv_bfloat16 h[4], l[4];
#pragma unroll
    for (int e = 0; e < 4; e++) {
        h[e] = __float2bfloat16_rn(a[e]);
        l[e] = __float2bfloat16_rn(a[e] - __bfloat162float(h[e]));
    }
    uint2 hh, ll;
    {
        __nv_bfloat162 p0(h[0], h[1]), p1(h[2], h[3]);
        hh.x = *reinterpret_cast<uint32_t*>(&p0); hh.y = *reinterpret_cast<uint32_t*>(&p1);
        __nv_bfloat162 q0(l[0], l[1]), q1(l[2], l[3]);
        ll.x = *reinterpret_cast<uint32_t*>(&q0); ll.y = *reinterpret_cast<uint32_t*>(&q1);
    }
    size_t ro = (size_t)r * KB3;
    *reinterpret_cast<uint2*>(&Y[ro + k])            = hh;
    *reinterpret_cast<uint2*>(&Y[ro + DIMM + k])     = mode ? ll : hh;
    *reinterpret_cast<uint2*>(&Y[ro + 2 * DIMM + k]) = mode ? hh : ll;
}

// ---------------------------------------------------------------------------
// HMMA GEMM, cp.async 3-stage pipeline, job-selected epilogue.
// job = zbase + blockIdx.z: 0=Q->q_eff, 1=K->k_eff, 2=V->vt_hi/lo, 3=O->fp32
// ---------------------------------------------------------------------------
#define NST (KB3/32)   // 72
#define STG 3
#define TBYT (128*80)

__global__ __launch_bounds__(256, 2)
void gemm_hmma(int zbase,
               const __nv_bfloat16* __restrict__ A0, const __nv_bfloat16* __restrict__ A1,
               const __nv_bfloat16* __restrict__ A2, const __nv_bfloat16* __restrict__ A3,
               const __nv_bfloat16* __restrict__ W0, const __nv_bfloat16* __restrict__ W1,
               const __nv_bfloat16* __restrict__ W2, const __nv_bfloat16* __restrict__ W3,
               const float* __restrict__ bq, const float* __restrict__ bk,
               const float* __restrict__ bv, const float* __restrict__ bo,
               float* __restrict__ outf,
               __nv_bfloat16* __restrict__ qe, __nv_bfloat16* __restrict__ kee,
               __nv_bfloat16* __restrict__ vh, __nv_bfloat16* __restrict__ vl)
{
    __shared__ __align__(16) unsigned char smA[STG][TBYT];
    __shared__ __align__(16) unsigned char smB[STG][TBYT];

    const int job = zbase + blockIdx.z;
    const __nv_bfloat16* A; const __nv_bfloat16* B; const float* bias;
    switch (job) {
        case 0: A = A0; B = W0; bias = bq; break;
        case 1: A = A1; B = W1; bias = bk; break;
        case 2: A = A2; B = W2; bias = bv; break;
        default: A = A3; B = W3; bias = bo; break;
    }

    const int tid    = threadIdx.x;
    const int lane   = tid & 31;
    const int wid    = tid >> 5;
    const int warp_m = wid & 1;
    const int warp_n = wid >> 1;
    const int bm = blockIdx.y * 128;
    const int bn = blockIdx.x * 128;

    const int lc  = tid & 3;
    const int lr0 = tid >> 2;
    const uint32_t smAu = smem_u32(smA);
    const uint32_t smBu = smem_u32(smB);

    float acc[4][4][4];
#pragma unroll
    for (int i = 0; i < 4; i++)
#pragma unroll
        for (int j = 0; j < 4; j++)
#pragma unroll
            for (int e = 0; e < 4; e++) acc[i][j][e] = 0.f;

    auto issue = [&](int s) {
        const size_t ke_ = (size_t)s * 32 + lc * 8;
        const uint32_t bo_ = (uint32_t)(s % STG) * TBYT;
#pragma unroll
        for (int p = 0; p < 2; p++) {
            int r = lr0 + 64 * p;
            cpa16(smAu + bo_ + r * 80 + lc * 16, &A[(size_t)(bm + r) * KB3 + ke_]);
            cpa16(smBu + bo_ + r * 80 + lc * 16, &B[(size_t)(bn + r) * KB3 + ke_]);
        }
        CPA_COMMIT();
    };

    issue(0);
    issue(1);

    for (int s = 0; s < NST; s++) {
        if (s + 2 < NST) CPA_WAIT1(); else CPA_WAIT0();
        __syncthreads();
        if (s + 2 < NST) issue(s + 2);

        const uint32_t bo_ = (uint32_t)(s % STG) * TBYT;
#pragma unroll
        for (int kk = 0; kk < 2; kk++) {
            uint32_t af[4][4], bf[4][2];
            const int achk = kk * 2 + (lane >> 4);
            const int arow0 = warp_m * 64 + (lane & 15);
#pragma unroll
            for (int mt = 0; mt < 4; mt++)
                ldsm_x4(af[mt], smAu + bo_ + (arow0 + mt * 16) * 80 + achk * 16);
            const int bchk = kk * 2 + ((lane >> 3) & 1);
            const int brow0 = warp_n * 32 + (lane & 7);
#pragma unroll
            for (int nt = 0; nt < 4; nt++)
                ldsm_x2(bf[nt], smBu + bo_ + (brow0 + nt * 8) * 80 + bchk * 16);
#pragma unroll
            for (int mt = 0; mt < 4; mt++)
#pragma unroll
                for (int nt = 0; nt < 4; nt++)
                    mma_bf16(acc[mt][nt], af[mt], bf[nt]);
        }
        __syncthreads();
    }

    // ---- epilogue ----
    const int rbase = bm + warp_m * 64 + (lane >> 2);
    const int cbase = bn + warp_n * 32 + (lane & 3) * 2;
#pragma unroll
    for (int mt = 0; mt < 4; mt++) {
#pragma unroll
        for (int nt = 0; nt < 4; nt++) {
            const int col = cbase + nt * 8;
            const float b0 = bias[col], b1 = bias[col + 1];
            const int r0 = rbase + mt * 16;
#pragma unroll
            for (int rh = 0; rh < 2; rh++) {
                const int row = r0 + rh * 8;
                float x0 = acc[mt][nt][rh * 2 + 0] + b0;
                float x1 = acc[mt][nt][rh * 2 + 1] + b1;
                if (job == 3) {
                    float2 v = {x0, x1};
                    *reinterpret_cast<float2*>(&outf[(size_t)row * DIMM + col]) = v;
                } else {
                    const int b_  = row >> 11, pos = row & 2047;
                    const int h_  = col >> 6,  d   = col & 63;
                    if (job == 0) { x0 *= 0.125f; x1 *= 0.125f; }
                    __nv_bfloat16 h0 = __float2bfloat16_rn(x0);
                    __nv_bfloat16 h1 = __float2bfloat16_rn(x1);
                    float l0f = x0 - __bfloat162float(h0);
                    float l1f = x1 - __bfloat162float(h1);
                    if (job == 2) {
                        size_t base = ((size_t)(b_ * NH + h_) * DH + d) * SEQ + pos;
                        vh[base]       = h0;
                        vh[base + SEQ] = h1;
                        vl[base]       = __float2bfloat16_rn(l0f);
                        vl[base + SEQ] = __float2bfloat16_rn(l1f);
                    } else {
                        __nv_bfloat162 hhp(h0, h1);
                        uint32_t hh = *reinterpret_cast<uint32_t*>(&hhp);
                        uint32_t ll = packbf(l0f, l1f);
                        __nv_bfloat16* dst = (job == 0) ? qe : kee;
                        size_t base = ((size_t)(b_ * NH + h_) * SEQ + pos) * KE + d;
                        *reinterpret_cast<uint32_t*>(dst + base)       = hh;
                        *reinterpret_cast<uint32_t*>(dst + base + 64)  = (job == 0) ? hh : ll;
                        *reinterpret_cast<uint32_t*>(dst + base + 128) = (job == 0) ? ll : hh;
                    }
                }
            }
        }
    }
}

// ---------------------------------------------------------------------------
// HMMA flash attention (unchanged from round 4).
// ---------------------------------------------------------------------------
#define BR 256
#define BK 64
#define QP 400
#define VP 144
#define QS_OFF 0
#define KS_OFF 102400
#define KBUF   25600
#define VH_OFF 153600
#define VBUF   9216
#define VL_OFF 172032
#define MS_OFF 190464
#define ATT_SMEM 190976

__global__ __launch_bounds__(256)
void attn_hmma(const __nv_bfloat16* __restrict__ qe, const __nv_bfloat16* __restrict__ ke,
               const __nv_bfloat16* __restrict__ vth, const __nv_bfloat16* __restrict__ vtl,
               const int* __restrict__ mask, __nv_bfloat16* __restrict__ ctx)
{
    extern __shared__ unsigned char sm[];
    const uint32_t smb = smem_u32(sm);
    const int tid  = threadIdx.x;
    const int lane = tid & 31;
    const int wid  = tid >> 5;
    const int q0   = blockIdx.x * BR;
    const int bh   = blockIdx.y;
    const int b    = bh / NH;
    const int h    = bh - b * NH;

    const __nv_bfloat16* qg = qe + ((size_t)bh * SEQ + q0) * KE;
    for (int idx = tid; idx < BR * 24; idx += 256) {
        int row = idx / 24, ch = idx - row * 24;
        cpa16(smb + QS_OFF + row * QP + ch * 16,
              reinterpret_cast<const char*>(qg + (size_t)row * KE) + ch * 16);
    }

    auto load_tile = [&](int kt, int buf) {
        const int k0 = kt * BK;
        const __nv_bfloat16* kg = ke + ((size_t)bh * SEQ + k0) * KE;
        for (int idx = tid; idx < 64 * 24; idx += 256) {
            int r = idx / 24, ch = idx - r * 24;
            cpa16(smb + KS_OFF + buf * KBUF + r * QP + ch * 16,
                  reinterpret_cast<const char*>(kg + (size_t)r * KE) + ch * 16);
        }
        const size_t vg = (size_t)bh * DH * SEQ + k0;
        for (int idx = tid; idx < 64 * 8; idx += 256) {
            int d = idx >> 3, ch = idx & 7;
            cpa16(smb + VH_OFF + buf * VBUF + d * VP + ch * 16,
                  reinterpret_cast<const char*>(vth + vg + (size_t)d * SEQ) + ch * 16);
            cpa16(smb + VL_OFF + buf * VBUF + d * VP + ch * 16,
                  reinterpret_cast<const char*>(vtl + vg + (size_t)d * SEQ) + ch * 16);
        }
        if (tid < 16)
            cpa16(smb + MS_OFF + buf * 256 + tid * 16,
                  reinterpret_cast<const char*>(mask + (size_t)b * SEQ + k0) + tid * 16);
    };

    load_tile(0, 0);
    CPA_COMMIT();

    float oacc[2][8][4];
    float m_[2][2], l_[2][2];
#pragma unroll
    for (int i = 0; i < 2; i++)
#pragma unroll
        for (int j = 0; j < 8; j++)
#pragma unroll
            for (int e = 0; e < 4; e++) oacc[i][j][e] = 0.f;
#pragma unroll
    for (int i = 0; i < 2; i++) { m_[i][0] = -1e30f; m_[i][1] = -1e30f; l_[i][0] = 0.f; l_[i][1] = 0.f; }

    const int l8  = lane & 7;
    const int ms1 = (lane >> 3) & 1;
    const int ms2 = (lane >> 4) & 1;
    const uint32_t qrowadr = smb + QS_OFF + (wid * 32 + l8 + ms1 * 8) * QP + ms2 * 16;
    const uint32_t krowadr0 = smb + KS_OFF + (l8 + ms1 * 8) * QP + ms2 * 16;
    const int l16 = lane & 15;
    const uint32_t vrowadr0h = smb + VH_OFF + (l16 & 7) * VP + ((l16 >> 3) * 16);
    const uint32_t vrowadr0l = smb + VL_OFF + (l16 & 7) * VP + ((l16 >> 3) * 16);
    const int qc = (lane & 3) * 2;
    const int* Msm = reinterpret_cast<const int*>(sm + MS_OFF);

    for (int kt = 0; kt < SEQ / BK; kt++) {
        const int buf = kt & 1;
        if (kt + 1 < SEQ / BK) {
            load_tile(kt + 1, buf ^ 1);
            CPA_COMMIT();
            CPA_WAIT1();
        } else {
            CPA_WAIT0();
        }
        __syncthreads();

        float sacc[2][8][4];
#pragma unroll
        for (int i = 0; i < 2; i++)
#pragma unroll
            for (int j = 0; j < 8; j++)
#pragma unroll
                for (int e = 0; e < 4; e++) sacc[i][j][e] = 0.f;

#pragma unroll
        for (int ks = 0; ks < KE / 16; ks++) {
            uint32_t af[2][4], bf[8][2];
#pragma unroll
            for (int mi = 0; mi < 2; mi++)
                ldsm_x4(af[mi], qrowadr + mi * (16 * QP) + ks * 32);
#pragma unroll
            for (int j = 0; j < 4; j++) {
                uint32_t t4[4];
                ldsm_x4(t4, krowadr0 + buf * KBUF + j * (16 * QP) + ks * 32);
                bf[2 * j][0] = t4[0]; bf[2 * j][1] = t4[2];
                bf[2 * j + 1][0] = t4[1]; bf[2 * j + 1][1] = t4[3];
            }
#pragma unroll
            for (int n = 0; n < 8; n++)
#pragma unroll
                for (int mi = 0; mi < 2; mi++)
                    mma_bf16(sacc[mi][n], af[mi], bf[n]);
        }

        const int mbase = buf * 64 + qc;
#pragma unroll
        for (int mi = 0; mi < 2; mi++) {
#pragma unroll
            for (int rh = 0; rh < 2; rh++) {
                float mx = -1e30f;
#pragma unroll
                for (int j = 0; j < 8; j++) {
#pragma unroll
                    for (int c = 0; c < 2; c++) {
                        float v = sacc[mi][j][rh * 2 + c];
                        int mk = Msm[mbase + j * 8 + c];
                        v = mk ? v : -1e30f;
                        sacc[mi][j][rh * 2 + c] = v;
                        mx = fmaxf(mx, v);
                    }
                }
                mx = fmaxf(mx, __shfl_xor_sync(0xffffffffu, mx, 1));
                mx = fmaxf(mx, __shfl_xor_sync(0xffffffffu, mx, 2));
                const float mn = fmaxf(m_[mi][rh], mx);
                const float al = __expf(m_[mi][rh] - mn);
                float sum = 0.f;
#pragma unroll
                for (int j = 0; j < 8; j++) {
#pragma unroll
                    for (int c = 0; c < 2; c++) {
                        float p = __expf(sacc[mi][j][rh * 2 + c] - mn);
                        sacc[mi][j][rh * 2 + c] = p;
                        sum += p;
                    }
                }
                sum += __shfl_xor_sync(0xffffffffu, sum, 1);
                sum += __shfl_xor_sync(0xffffffffu, sum, 2);
                l_[mi][rh] = l_[mi][rh] * al + sum;
                m_[mi][rh] = mn;
#pragma unroll
                for (int j = 0; j < 8; j++) {
                    oacc[mi][j][rh * 2 + 0] *= al;
                    oacc[mi][j][rh * 2 + 1] *= al;
                }
            }
        }

#pragma unroll
        for (int t = 0; t < 4; t++) {
            uint32_t vhf[8][2], vlf[8][2];
#pragma unroll
            for (int n = 0; n < 8; n++) {
                ldsm_x2(vhf[n], vrowadr0h + buf * VBUF + n * (8 * VP) + t * 32);
                ldsm_x2(vlf[n], vrowadr0l + buf * VBUF + n * (8 * VP) + t * 32);
            }
#pragma unroll
            for (int mi = 0; mi < 2; mi++) {
                uint32_t ah[4], alr[4];
#pragma unroll
                for (int half = 0; half < 2; half++) {
                    const float* s4 = sacc[mi][2 * t + half];
#pragma unroll
                    for (int rh = 0; rh < 2; rh++) {
                        float p0 = s4[rh * 2 + 0], p1 = s4[rh * 2 + 1];
                        __nv_bfloat16 h0 = __float2bfloat16_rn(p0);
                        __nv_bfloat16 h1 = __float2bfloat16_rn(p1);
                        __nv_bfloat162 hp(h0, h1);
                        ah[half * 2 + rh]  = *reinterpret_cast<uint32_t*>(&hp);
                        alr[half * 2 + rh] = packbf(p0 - __bfloat162float(h0),
                                                    p1 - __bfloat162float(h1));
                    }
                }
                uint32_t A_h[4] = {ah[0], ah[1], ah[2], ah[3]};
                uint32_t A_l[4] = {alr[0], alr[1], alr[2], alr[3]};
#pragma unroll
                for (int n = 0; n < 8; n++) {
                    mma_bf16(oacc[mi][n], A_h, vhf[n]);
                    mma_bf16(oacc[mi][n], A_h, vlf[n]);
                    mma_bf16(oacc[mi][n], A_l, vhf[n]);
                }
            }
        }
        __syncthreads();
    }

#pragma unroll
    for (int mi = 0; mi < 2; mi++) {
#pragma unroll
        for (int rh = 0; rh < 2; rh++) {
            const int row = wid * 32 + mi * 16 + rh * 8 + (lane >> 2);
            const float inv = 1.f / l_[mi][rh];
            const size_t tb = (size_t)(b * SEQ + q0 + row) * KB3 + h * 64 + qc;
#pragma unroll
            for (int j = 0; j < 8; j++) {
                float x0 = oacc[mi][j][rh * 2 + 0] * inv;
                float x1 = oacc[mi][j][rh * 2 + 1] * inv;
                __nv_bfloat16 h0 = __float2bfloat16_rn(x0);
                __nv_bfloat16 h1 = __float2bfloat16_rn(x1);
                __nv_bfloat162 hp(h0, h1);
                uint32_t hh = *reinterpret_cast<uint32_t*>(&hp);
                uint32_t ll = packbf(x0 - __bfloat162float(h0), x1 - __bfloat162float(h1));
                __nv_bfloat16* dst = ctx + tb + j * 8;
                *reinterpret_cast<uint32_t*>(dst)            = hh;
                *reinterpret_cast<uint32_t*>(dst + DIMM)     = hh;
                *reinterpret_cast<uint32_t*>(dst + 2 * DIMM) = ll;
            }
        }
    }
}

// ---------------------------------------------------------------------------
extern "C" void kernel_launch(void* const* d_in, const int* in_sizes, int n_in,
                              void* d_out, int out_size)
{
    const float* query = (const float*)d_in[0];
    const float* key_t = (const float*)d_in[1];
    const float* value = (const float*)d_in[2];
    const int*   mask  = (const int*)  d_in[3];
    const float* q_w   = (const float*)d_in[4];
    const float* q_b   = (const float*)d_in[5];
    const float* k_w   = (const float*)d_in[6];
    const float* k_b   = (const float*)d_in[7];
    const float* v_w   = (const float*)d_in[8];
    const float* v_b   = (const float*)d_in[9];
    const float* o_w   = (const float*)d_in[10];
    const float* o_b   = (const float*)d_in[11];
    float* out = (float*)d_out;

    __nv_bfloat16 *a0, *a1, *a2, *w0, *w1, *w2, *w3, *gqe, *gke, *gvh, *gvl, *gce;
    cudaGetSymbolAddress((void**)&a0, g_a0);
    cudaGetSymbolAddress((void**)&a1, g_a1);
    cudaGetSymbolAddress((void**)&a2, g_a2);
    cudaGetSymbolAddress((void**)&w0, g_w0);
    cudaGetSymbolAddress((void**)&w1, g_w1);
    cudaGetSymbolAddress((void**)&w2, g_w2);
    cudaGetSymbolAddress((void**)&w3, g_w3);
    cudaGetSymbolAddress((void**)&gqe, g_qe);
    cudaGetSymbolAddress((void**)&gke, g_ke);
    cudaGetSymbolAddress((void**)&gvh, g_vth);
    cudaGetSymbolAddress((void**)&gvl, g_vtl);
    cudaGetSymbolAddress((void**)&gce, g_ce);

    cudaFuncSetAttribute(attn_hmma,
                         cudaFuncAttributeMaxDynamicSharedMemorySize, ATT_SMEM);

    // 1. all splits, one launch
    split_all<<<dim3((NTOK * 192 + 255) / 256, 7), 256>>>(
        query, key_t, value, q_w, k_w, v_w, o_w, a0, a1, a2, w0, w1, w2, w3);

    // 2. Q,K,V projections fused in one launch (grid.z = 3)
    gemm_hmma<<<dim3(DIMM / 128, NTOK / 128, 3), 256>>>(
        0, a0, a1, a2, gce, w0, w1, w2, w3, q_b, k_b, v_b, o_b,
        nullptr, gqe, gke, gvh, gvl);

    // 3. attention
    attn_hmma<<<dim3(SEQ / BR, BSZ * NH), 256, ATT_SMEM>>>(gqe, gke, gvh, gvl, mask, gce);

    // 4. output projection
    gemm_hmma<<<dim3(DIMM / 128, NTOK / 128, 1), 256>>>(
        3, a0, a1, a2, gce, w0, w1, w2, w3, q_b, k_b, v_b, o_b,
        out, gqe, gke, gvh, gvl);
}

// round 6
// speedup vs baseline: 2.9892x; 1.0673x over previous
#include <cuda_runtime.h>
#include <cuda_bf16.h>
#include <math.h>
#include <cstdint>

#define BSZ  4
#define SEQ  2048
#define DIMM 768
#define NH   12
#define DH   64
#define NTOK (BSZ*SEQ)   // 8192
#define KB3  (3*DIMM)    // 2304
#define KE   192

// ---------------- scratch (device globals) ----------------------------------
__device__ __align__(256) __nv_bfloat16 g_a0 [(size_t)NTOK*KB3];
__device__ __align__(256) __nv_bfloat16 g_a1 [(size_t)NTOK*KB3];
__device__ __align__(256) __nv_bfloat16 g_a2 [(size_t)NTOK*KB3];
__device__ __align__(256) __nv_bfloat16 g_w0 [(size_t)DIMM*KB3];
__device__ __align__(256) __nv_bfloat16 g_w1 [(size_t)DIMM*KB3];
__device__ __align__(256) __nv_bfloat16 g_w2 [(size_t)DIMM*KB3];
__device__ __align__(256) __nv_bfloat16 g_w3 [(size_t)DIMM*KB3];
__device__ __align__(256) __nv_bfloat16 g_qe [(size_t)BSZ*NH*SEQ*KE];
__device__ __align__(256) __nv_bfloat16 g_ke [(size_t)BSZ*NH*SEQ*KE];
__device__ __align__(256) __nv_bfloat16 g_vth[(size_t)BSZ*NH*DH*SEQ];
__device__ __align__(256) __nv_bfloat16 g_vtl[(size_t)BSZ*NH*DH*SEQ];
__device__ __align__(256) __nv_bfloat16 g_ce [(size_t)NTOK*KB3];

// ---------------- helpers ---------------------------------------------------
__device__ __forceinline__ uint32_t smem_u32(const void* p) {
    uint32_t a;
    asm("{ .reg .u64 t; cvta.to.shared.u64 t, %1; cvt.u32.u64 %0, t; }" : "=r"(a) : "l"(p));
    return a;
}
__device__ __forceinline__ void ldsm_x4(uint32_t* r, uint32_t addr) {
    asm volatile("ldmatrix.sync.aligned.m8n8.x4.shared.b16 {%0,%1,%2,%3}, [%4];"
                 : "=r"(r[0]), "=r"(r[1]), "=r"(r[2]), "=r"(r[3]) : "r"(addr));
}
__device__ __forceinline__ void ldsm_x2(uint32_t* r, uint32_t addr) {
    asm volatile("ldmatrix.sync.aligned.m8n8.x2.shared.b16 {%0,%1}, [%2];"
                 : "=r"(r[0]), "=r"(r[1]) : "r"(addr));
}
__device__ __forceinline__ void mma_bf16(float* d, const uint32_t* a, const uint32_t* b) {
    asm volatile(
        "mma.sync.aligned.m16n8k16.row.col.f32.bf16.bf16.f32 "
        "{%0,%1,%2,%3}, {%4,%5,%6,%7}, {%8,%9}, {%0,%1,%2,%3};"
        : "+f"(d[0]), "+f"(d[1]), "+f"(d[2]), "+f"(d[3])
        : "r"(a[0]), "r"(a[1]), "r"(a[2]), "r"(a[3]), "r"(b[0]), "r"(b[1]));
}
__device__ __forceinline__ void cpa16(uint32_t dst, const void* src) {
    asm volatile("cp.async.cg.shared.global [%0], [%1], 16;" :: "r"(dst), "l"(src));
}
#define CPA_COMMIT() asm volatile("cp.async.commit_group;" ::: "memory")
#define CPA_WAIT1()  asm volatile("cp.async.wait_group 1;" ::: "memory")
#define CPA_WAIT0()  asm volatile("cp.async.wait_group 0;" ::: "memory")

__device__ __forceinline__ uint32_t packbf(float a, float b) {
    __nv_bfloat162 t(__float2bfloat16_rn(a), __float2bfloat16_rn(b));
    return *reinterpret_cast<uint32_t*>(&t);
}

// ---------------------------------------------------------------------------
// Fused split: all 7 tensors in one launch (blockIdx.y = job).
// ---------------------------------------------------------------------------
__global__ void split_all(const float* __restrict__ q, const float* __restrict__ kt,
                          const float* __restrict__ v,
                          const float* __restrict__ qw, const float* __restrict__ kw,
                          const float* __restrict__ vw, const float* __restrict__ ow,
                          __nv_bfloat16* __restrict__ a0, __nv_bfloat16* __restrict__ a1,
                          __nv_bfloat16* __restrict__ a2, __nv_bfloat16* __restrict__ w0,
                          __nv_bfloat16* __restrict__ w1, __nv_bfloat16* __restrict__ w2,
                          __nv_bfloat16* __restrict__ w3)
{
    const int job = blockIdx.y;
    const float* X; __nv_bfloat16* Y; int rows, mode;
    switch (job) {
        case 0: X = q;  Y = a0; rows = NTOK; mode = 0; break;
        case 1: X = kt; Y = a1; rows = NTOK; mode = 0; break;
        case 2: X = v;  Y = a2; rows = NTOK; mode = 0; break;
        case 3: X = qw; Y = w0; rows = DIMM; mode = 1; break;
        case 4: X = kw; Y = w1; rows = DIMM; mode = 1; break;
        case 5: X = vw; Y = w2; rows = DIMM; mode = 1; break;
        default: X = ow; Y = w3; rows = DIMM; mode = 1; break;
    }
    const int nquads = rows * 192;
    int i = blockIdx.x * blockDim.x + threadIdx.x;
    if (i >= nquads) return;
    int r = i / 192;
    int k = (i % 192) * 4;
    float4 vv = *reinterpret_cast<const float4*>(&X[(size_t)r * DIMM + k]);
    float a[4] = {vv.x, vv.y, vv.z, vv.w};
    __nv_bfloat16 h[4], l[4];
#pragma unroll
    for (int e = 0; e < 4; e++) {
        h[e] = __float2bfloat16_rn(a[e]);
        l[e] = __float2bfloat16_rn(a[e] - __bfloat162float(h[e]));
    }
    uint2 hh, ll;
    {
        __nv_bfloat162 p0(h[0], h[1]), p1(h[2], h[3]);
        hh.x = *reinterpret_cast<uint32_t*>(&p0); hh.y = *reinterpret_cast<uint32_t*>(&p1);
        __nv_bfloat162 q0(l[0], l[1]), q1(l[2], l[3]);
        ll.x = *reinterpret_cast<uint32_t*>(&q0); ll.y = *reinterpret_cast<uint32_t*>(&q1);
    }
    size_t ro = (size_t)r * KB3;
    *reinterpret_cast<uint2*>(&Y[ro + k])            = hh;
    *reinterpret_cast<uint2*>(&Y[ro + DIMM + k])     = mode ? ll : hh;
    *reinterpret_cast<uint2*>(&Y[ro + 2 * DIMM + k]) = mode ? hh : ll;
}

// ---------------------------------------------------------------------------
// HMMA GEMM: BK=64, 3-stage cp.async, ONE barrier per stage, pitch 144.
// job = zbase + blockIdx.z: 0=Q->q_eff, 1=K->k_eff, 2=V->vt_hi/lo, 3=O->fp32
// ---------------------------------------------------------------------------
#define NST (KB3/64)     // 36
#define STG 3
#define GPITCH 144
#define STGB (128*GPITCH)          // 18432 per matrix
#define GSMEM (STG*2*STGB)         // 110592

__global__ __launch_bounds__(256, 2)
void gemm_hmma(int zbase,
               const __nv_bfloat16* __restrict__ A0, const __nv_bfloat16* __restrict__ A1,
               const __nv_bfloat16* __restrict__ A2, const __nv_bfloat16* __restrict__ A3,
               const __nv_bfloat16* __restrict__ W0, const __nv_bfloat16* __restrict__ W1,
               const __nv_bfloat16* __restrict__ W2, const __nv_bfloat16* __restrict__ W3,
               const float* __restrict__ bq, const float* __restrict__ bk,
               const float* __restrict__ bv, const float* __restrict__ bo,
               float* __restrict__ outf,
               __nv_bfloat16* __restrict__ qe, __nv_bfloat16* __restrict__ kee,
               __nv_bfloat16* __restrict__ vh, __nv_bfloat16* __restrict__ vl)
{
    extern __shared__ unsigned char smg[];

    const int job = zbase + blockIdx.z;
    const __nv_bfloat16* A; const __nv_bfloat16* B; const float* bias;
    switch (job) {
        case 0: A = A0; B = W0; bias = bq; break;
        case 1: A = A1; B = W1; bias = bk; break;
        case 2: A = A2; B = W2; bias = bv; break;
        default: A = A3; B = W3; bias = bo; break;
    }

    const int tid    = threadIdx.x;
    const int lane   = tid & 31;
    const int wid    = tid >> 5;
    const int warp_m = wid & 1;
    const int warp_n = wid >> 1;
    const int bm = blockIdx.y * 128;
    const int bn = blockIdx.x * 128;

    const int lc  = tid & 7;      // 16B chunk within 128B row-slab
    const int lr0 = tid >> 3;     // 0..31
    const uint32_t smu = smem_u32(smg);

    float acc[4][4][4];
#pragma unroll
    for (int i = 0; i < 4; i++)
#pragma unroll
        for (int j = 0; j < 4; j++)
#pragma unroll
            for (int e = 0; e < 4; e++) acc[i][j][e] = 0.f;

    auto issue = [&](int s) {
        const size_t ke_ = (size_t)s * 64 + lc * 8;
        const uint32_t bo_ = (uint32_t)(s % STG) * (2 * STGB);
#pragma unroll
        for (int p = 0; p < 4; p++) {
            int r = lr0 + 32 * p;
            cpa16(smu + bo_ + r * GPITCH + lc * 16,         &A[(size_t)(bm + r) * KB3 + ke_]);
            cpa16(smu + bo_ + STGB + r * GPITCH + lc * 16,  &B[(size_t)(bn + r) * KB3 + ke_]);
        }
        CPA_COMMIT();
    };

    issue(0);
    issue(1);

    const int arow0 = warp_m * 64 + (lane & 15);
    const int acol  = (lane >> 4) * 16;
    const int brow0 = warp_n * 32 + (lane & 7);
    const int bcol  = ((lane >> 3) & 1) * 16;

    for (int s = 0; s < NST; s++) {
        if (s + 2 < NST) CPA_WAIT1(); else CPA_WAIT0();
        __syncthreads();
        if (s + 2 < NST) issue(s + 2);

        const uint32_t bo_ = (uint32_t)(s % STG) * (2 * STGB);
#pragma unroll
        for (int ks = 0; ks < 4; ks++) {
            uint32_t af[4][4], bf[4][2];
#pragma unroll
            for (int mt = 0; mt < 4; mt++)
                ldsm_x4(af[mt], smu + bo_ + (arow0 + mt * 16) * GPITCH + ks * 32 + acol);
#pragma unroll
            for (int nt = 0; nt < 4; nt++)
                ldsm_x2(bf[nt], smu + bo_ + STGB + (brow0 + nt * 8) * GPITCH + ks * 32 + bcol);
#pragma unroll
            for (int mt = 0; mt < 4; mt++)
#pragma unroll
                for (int nt = 0; nt < 4; nt++)
                    mma_bf16(acc[mt][nt], af[mt], bf[nt]);
        }
        // no trailing barrier: next iteration's top barrier protects buffers
    }

    // ---- epilogue ----
    const int rbase = bm + warp_m * 64 + (lane >> 2);
    const int cbase = bn + warp_n * 32 + (lane & 3) * 2;
#pragma unroll
    for (int mt = 0; mt < 4; mt++) {
#pragma unroll
        for (int nt = 0; nt < 4; nt++) {
            const int col = cbase + nt * 8;
            const float b0 = bias[col], b1 = bias[col + 1];
            const int r0 = rbase + mt * 16;
#pragma unroll
            for (int rh = 0; rh < 2; rh++) {
                const int row = r0 + rh * 8;
                float x0 = acc[mt][nt][rh * 2 + 0] + b0;
                float x1 = acc[mt][nt][rh * 2 + 1] + b1;
                if (job == 3) {
                    float2 v = {x0, x1};
                    *reinterpret_cast<float2*>(&outf[(size_t)row * DIMM + col]) = v;
                } else {
                    const int b_  = row >> 11, pos = row & 2047;
                    const int h_  = col >> 6,  d   = col & 63;
                    if (job == 0) { x0 *= 0.125f; x1 *= 0.125f; }
                    __nv_bfloat16 h0 = __float2bfloat16_rn(x0);
                    __nv_bfloat16 h1 = __float2bfloat16_rn(x1);
                    float l0f = x0 - __bfloat162float(h0);
                    float l1f = x1 - __bfloat162float(h1);
                    if (job == 2) {
                        size_t base = ((size_t)(b_ * NH + h_) * DH + d) * SEQ + pos;
                        vh[base]       = h0;
                        vh[base + SEQ] = h1;
                        vl[base]       = __float2bfloat16_rn(l0f);
                        vl[base + SEQ] = __float2bfloat16_rn(l1f);
                    } else {
                        __nv_bfloat162 hhp(h0, h1);
                        uint32_t hh = *reinterpret_cast<uint32_t*>(&hhp);
                        uint32_t ll = packbf(l0f, l1f);
                        __nv_bfloat16* dst = (job == 0) ? qe : kee;
                        size_t base = ((size_t)(b_ * NH + h_) * SEQ + pos) * KE + d;
                        *reinterpret_cast<uint32_t*>(dst + base)       = hh;
                        *reinterpret_cast<uint32_t*>(dst + base + 64)  = (job == 0) ? hh : ll;
                        *reinterpret_cast<uint32_t*>(dst + base + 128) = (job == 0) ? ll : hh;
                    }
                }
            }
        }
    }
}

// ---------------------------------------------------------------------------
// HMMA flash attention; single barrier per tile (wait -> sync -> issue -> compute).
// ---------------------------------------------------------------------------
#define BR 256
#define BK 64
#define QP 400
#define VP 144
#define QS_OFF 0
#define KS_OFF 102400
#define KBUF   25600
#define VH_OFF 153600
#define VBUF   9216
#define VL_OFF 172032
#define MS_OFF 190464
#define ATT_SMEM 190976

__global__ __launch_bounds__(256)
void attn_hmma(const __nv_bfloat16* __restrict__ qe, const __nv_bfloat16* __restrict__ ke,
               const __nv_bfloat16* __restrict__ vth, const __nv_bfloat16* __restrict__ vtl,
               const int* __restrict__ mask, __nv_bfloat16* __restrict__ ctx)
{
    extern __shared__ unsigned char sm[];
    const uint32_t smb = smem_u32(sm);
    const int tid  = threadIdx.x;
    const int lane = tid & 31;
    const int wid  = tid >> 5;
    const int q0   = blockIdx.x * BR;
    const int bh   = blockIdx.y;
    const int b    = bh / NH;
    const int h    = bh - b * NH;

    const __nv_bfloat16* qg = qe + ((size_t)bh * SEQ + q0) * KE;
    for (int idx = tid; idx < BR * 24; idx += 256) {
        int row = idx / 24, ch = idx - row * 24;
        cpa16(smb + QS_OFF + row * QP + ch * 16,
              reinterpret_cast<const char*>(qg + (size_t)row * KE) + ch * 16);
    }

    auto load_tile = [&](int kt, int buf) {
        const int k0 = kt * BK;
        const __nv_bfloat16* kg = ke + ((size_t)bh * SEQ + k0) * KE;
        for (int idx = tid; idx < 64 * 24; idx += 256) {
            int r = idx / 24, ch = idx - r * 24;
            cpa16(smb + KS_OFF + buf * KBUF + r * QP + ch * 16,
                  reinterpret_cast<const char*>(kg + (size_t)r * KE) + ch * 16);
        }
        const size_t vg = (size_t)bh * DH * SEQ + k0;
        for (int idx = tid; idx < 64 * 8; idx += 256) {
            int d = idx >> 3, ch = idx & 7;
            cpa16(smb + VH_OFF + buf * VBUF + d * VP + ch * 16,
                  reinterpret_cast<const char*>(vth + vg + (size_t)d * SEQ) + ch * 16);
            cpa16(smb + VL_OFF + buf * VBUF + d * VP + ch * 16,
                  reinterpret_cast<const char*>(vtl + vg + (size_t)d * SEQ) + ch * 16);
        }
        if (tid < 16)
            cpa16(smb + MS_OFF + buf * 256 + tid * 16,
                  reinterpret_cast<const char*>(mask + (size_t)b * SEQ + k0) + tid * 16);
    };

    load_tile(0, 0);
    CPA_COMMIT();

    float oacc[2][8][4];
    float m_[2][2], l_[2][2];
#pragma unroll
    for (int i = 0; i < 2; i++)
#pragma unroll
        for (int j = 0; j < 8; j++)
#pragma unroll
            for (int e = 0; e < 4; e++) oacc[i][j][e] = 0.f;
#pragma unroll
    for (int i = 0; i < 2; i++) { m_[i][0] = -1e30f; m_[i][1] = -1e30f; l_[i][0] = 0.f; l_[i][1] = 0.f; }

    const int l8  = lane & 7;
    const int ms1 = (lane >> 3) & 1;
    const int ms2 = (lane >> 4) & 1;
    const uint32_t qrowadr = smb + QS_OFF + (wid * 32 + l8 + ms1 * 8) * QP + ms2 * 16;
    const uint32_t krowadr0 = smb + KS_OFF + (l8 + ms1 * 8) * QP + ms2 * 16;
    const int l16 = lane & 15;
    const uint32_t vrowadr0h = smb + VH_OFF + (l16 & 7) * VP + ((l16 >> 3) * 16);
    const uint32_t vrowadr0l = smb + VL_OFF + (l16 & 7) * VP + ((l16 >> 3) * 16);
    const int qc = (lane & 3) * 2;
    const int* Msm = reinterpret_cast<const int*>(sm + MS_OFF);

    for (int kt = 0; kt < SEQ / BK; kt++) {
        const int buf = kt & 1;
        CPA_WAIT0();
        __syncthreads();
        if (kt + 1 < SEQ / BK) {
            load_tile(kt + 1, buf ^ 1);
            CPA_COMMIT();
        }

        float sacc[2][8][4];
#pragma unroll
        for (int i = 0; i < 2; i++)
#pragma unroll
            for (int j = 0; j < 8; j++)
#pragma unroll
                for (int e = 0; e < 4; e++) sacc[i][j][e] = 0.f;

#pragma unroll
        for (int ks = 0; ks < KE / 16; ks++) {
            uint32_t af[2][4], bf[8][2];
#pragma unroll
            for (int mi = 0; mi < 2; mi++)
                ldsm_x4(af[mi], qrowadr + mi * (16 * QP) + ks * 32);
#pragma unroll
            for (int j = 0; j < 4; j++) {
                uint32_t t4[4];
                ldsm_x4(t4, krowadr0 + buf * KBUF + j * (16 * QP) + ks * 32);
                bf[2 * j][0] = t4[0]; bf[2 * j][1] = t4[2];
                bf[2 * j + 1][0] = t4[1]; bf[2 * j + 1][1] = t4[3];
            }
#pragma unroll
            for (int n = 0; n < 8; n++)
#pragma unroll
                for (int mi = 0; mi < 2; mi++)
                    mma_bf16(sacc[mi][n], af[mi], bf[n]);
        }

        const int mbase = buf * 64 + qc;
#pragma unroll
        for (int mi = 0; mi < 2; mi++) {
#pragma unroll
            for (int rh = 0; rh < 2; rh++) {
                float mx = -1e30f;
#pragma unroll
                for (int j = 0; j < 8; j++) {
#pragma unroll
                    for (int c = 0; c < 2; c++) {
                        float v = sacc[mi][j][rh * 2 + c];
                        int mk = Msm[mbase + j * 8 + c];
                        v = mk ? v : -1e30f;
                        sacc[mi][j][rh * 2 + c] = v;
                        mx = fmaxf(mx, v);
                    }
                }
                mx = fmaxf(mx, __shfl_xor_sync(0xffffffffu, mx, 1));
                mx = fmaxf(mx, __shfl_xor_sync(0xffffffffu, mx, 2));
                const float mn = fmaxf(m_[mi][rh], mx);
                const float al = __expf(m_[mi][rh] - mn);
                float sum = 0.f;
#pragma unroll
                for (int j = 0; j < 8; j++) {
#pragma unroll
                    for (int c = 0; c < 2; c++) {
                        float p = __expf(sacc[mi][j][rh * 2 + c] - mn);
                        sacc[mi][j][rh * 2 + c] = p;
                        sum += p;
                    }
                }
                sum += __shfl_xor_sync(0xffffffffu, sum, 1);
                sum += __shfl_xor_sync(0xffffffffu, sum, 2);
                l_[mi][rh] = l_[mi][rh] * al + sum;
                m_[mi][rh] = mn;
#pragma unroll
                for (int j = 0; j < 8; j++) {
                    oacc[mi][j][rh * 2 + 0] *= al;
                    oacc[mi][j][rh * 2 + 1] *= al;
                }
            }
        }

#pragma unroll
        for (int t = 0; t < 4; t++) {
            uint32_t vhf[8][2], vlf[8][2];
#pragma unroll
            for (int n = 0; n < 8; n++) {
                ldsm_x2(vhf[n], vrowadr0h + buf * VBUF + n * (8 * VP) + t * 32);
                ldsm_x2(vlf[n], vrowadr0l + buf * VBUF + n * (8 * VP) + t * 32);
            }
#pragma unroll
            for (int mi = 0; mi < 2; mi++) {
                uint32_t ah[4], alr[4];
#pragma unroll
                for (int half = 0; half < 2; half++) {
                    const float* s4 = sacc[mi][2 * t + half];
#pragma unroll
                    for (int rh = 0; rh < 2; rh++) {
                        float p0 = s4[rh * 2 + 0], p1 = s4[rh * 2 + 1];
                        __nv_bfloat16 h0 = __float2bfloat16_rn(p0);
                        __nv_bfloat16 h1 = __float2bfloat16_rn(p1);
                        __nv_bfloat162 hp(h0, h1);
                        ah[half * 2 + rh]  = *reinterpret_cast<uint32_t*>(&hp);
                        alr[half * 2 + rh] = packbf(p0 - __bfloat162float(h0),
                                                    p1 - __bfloat162float(h1));
                    }
                }
                uint32_t A_h[4] = {ah[0], ah[1], ah[2], ah[3]};
                uint32_t A_l[4] = {alr[0], alr[1], alr[2], alr[3]};
#pragma unroll
                for (int n = 0; n < 8; n++) {
                    mma_bf16(oacc[mi][n], A_h, vhf[n]);
                    mma_bf16(oacc[mi][n], A_h, vlf[n]);
                    mma_bf16(oacc[mi][n], A_l, vhf[n]);
                }
            }
        }
        // no trailing barrier
    }

#pragma unroll
    for (int mi = 0; mi < 2; mi++) {
#pragma unroll
        for (int rh = 0; rh < 2; rh++) {
            const int row = wid * 32 + mi * 16 + rh * 8 + (lane >> 2);
            const float inv = 1.f / l_[mi][rh];
            const size_t tb = (size_t)(b * SEQ + q0 + row) * KB3 + h * 64 + qc;
#pragma unroll
            for (int j = 0; j < 8; j++) {
                float x0 = oacc[mi][j][rh * 2 + 0] * inv;
                float x1 = oacc[mi][j][rh * 2 + 1] * inv;
                __nv_bfloat16 h0 = __float2bfloat16_rn(x0);
                __nv_bfloat16 h1 = __float2bfloat16_rn(x1);
                __nv_bfloat162 hp(h0, h1);
                uint32_t hh = *reinterpret_cast<uint32_t*>(&hp);
                uint32_t ll = packbf(x0 - __bfloat162float(h0), x1 - __bfloat162float(h1));
                __nv_bfloat16* dst = ctx + tb + j * 8;
                *reinterpret_cast<uint32_t*>(dst)            = hh;
                *reinterpret_cast<uint32_t*>(dst + DIMM)     = hh;
                *reinterpret_cast<uint32_t*>(dst + 2 * DIMM) = ll;
            }
        }
    }
}

// ---------------------------------------------------------------------------
extern "C" void kernel_launch(void* const* d_in, const int* in_sizes, int n_in,
                              void* d_out, int out_size)
{
    const float* query = (const float*)d_in[0];
    const float* key_t = (const float*)d_in[1];
    const float* value = (const float*)d_in[2];
    const int*   mask  = (const int*)  d_in[3];
    const float* q_w   = (const float*)d_in[4];
    const float* q_b   = (const float*)d_in[5];
    const float* k_w   = (const float*)d_in[6];
    const float* k_b   = (const float*)d_in[7];
    const float* v_w   = (const float*)d_in[8];
    const float* v_b   = (const float*)d_in[9];
    const float* o_w   = (const float*)d_in[10];
    const float* o_b   = (const float*)d_in[11];
    float* out = (float*)d_out;

    __nv_bfloat16 *a0, *a1, *a2, *w0, *w1, *w2, *w3, *gqe, *gke, *gvh, *gvl, *gce;
    cudaGetSymbolAddress((void**)&a0, g_a0);
    cudaGetSymbolAddress((void**)&a1, g_a1);
    cudaGetSymbolAddress((void**)&a2, g_a2);
    cudaGetSymbolAddress((void**)&w0, g_w0);
    cudaGetSymbolAddress((void**)&w1, g_w1);
    cudaGetSymbolAddress((void**)&w2, g_w2);
    cudaGetSymbolAddress((void**)&w3, g_w3);
    cudaGetSymbolAddress((void**)&gqe, g_qe);
    cudaGetSymbolAddress((void**)&gke, g_ke);
    cudaGetSymbolAddress((void**)&gvh, g_vth);
    cudaGetSymbolAddress((void**)&gvl, g_vtl);
    cudaGetSymbolAddress((void**)&gce, g_ce);

    cudaFuncSetAttribute(attn_hmma,
                         cudaFuncAttributeMaxDynamicSharedMemorySize, ATT_SMEM);
    cudaFuncSetAttribute(gemm_hmma,
                         cudaFuncAttributeMaxDynamicSharedMemorySize, GSMEM);

    split_all<<<dim3((NTOK * 192 + 255) / 256, 7), 256>>>(
        query, key_t, value, q_w, k_w, v_w, o_w, a0, a1, a2, w0, w1, w2, w3);

    gemm_hmma<<<dim3(DIMM / 128, NTOK / 128, 3), 256, GSMEM>>>(
        0, a0, a1, a2, gce, w0, w1, w2, w3, q_b, k_b, v_b, o_b,
        nullptr, gqe, gke, gvh, gvl);

    attn_hmma<<<dim3(SEQ / BR, BSZ * NH), 256, ATT_SMEM>>>(gqe, gke, gvh, gvl, mask, gce);

    gemm_hmma<<<dim3(DIMM / 128, NTOK / 128, 1), 256, GSMEM>>>(
        3, a0, a1, a2, gce, w0, w1, w2, w3, q_b, k_b, v_b, o_b,
        out, gqe, gke, gvh, gvl);
}

// round 7
// speedup vs baseline: 3.5186x; 1.1771x over previous
#include <cuda_runtime.h>
#include <cuda_bf16.h>
#include <cuda_fp16.h>
#include <math.h>
#include <cstdint>

#define BSZ  4
#define SEQ  2048
#define DIMM 768
#define NH   12
#define DH   64
#define NTOK (BSZ*SEQ)   // 8192
#define KB3  (3*DIMM)    // 2304
#define KE   192

// ---------------- scratch (device globals) ----------------------------------
__device__ __align__(256) __nv_bfloat16 g_a0 [(size_t)NTOK*KB3];
__device__ __align__(256) __nv_bfloat16 g_a1 [(size_t)NTOK*KB3];
__device__ __align__(256) __nv_bfloat16 g_a2 [(size_t)NTOK*KB3];
__device__ __align__(256) __nv_bfloat16 g_w0 [(size_t)DIMM*KB3];
__device__ __align__(256) __nv_bfloat16 g_w1 [(size_t)DIMM*KB3];
__device__ __align__(256) __nv_bfloat16 g_w2 [(size_t)DIMM*KB3];
__device__ __align__(256) __nv_bfloat16 g_w3 [(size_t)DIMM*KB3];
__device__ __align__(256) __nv_bfloat16 g_qe [(size_t)BSZ*NH*SEQ*KE];
__device__ __align__(256) __nv_bfloat16 g_ke [(size_t)BSZ*NH*SEQ*KE];
__device__ __align__(256) __half        g_vt [(size_t)BSZ*NH*DH*SEQ];
__device__ __align__(256) __nv_bfloat16 g_ce [(size_t)NTOK*KB3];

// ---------------- helpers ---------------------------------------------------
__device__ __forceinline__ uint32_t smem_u32(const void* p) {
    uint32_t a;
    asm("{ .reg .u64 t; cvta.to.shared.u64 t, %1; cvt.u32.u64 %0, t; }" : "=r"(a) : "l"(p));
    return a;
}
__device__ __forceinline__ void ldsm_x4(uint32_t* r, uint32_t addr) {
    asm volatile("ldmatrix.sync.aligned.m8n8.x4.shared.b16 {%0,%1,%2,%3}, [%4];"
                 : "=r"(r[0]), "=r"(r[1]), "=r"(r[2]), "=r"(r[3]) : "r"(addr));
}
__device__ __forceinline__ void ldsm_x2(uint32_t* r, uint32_t addr) {
    asm volatile("ldmatrix.sync.aligned.m8n8.x2.shared.b16 {%0,%1}, [%2];"
                 : "=r"(r[0]), "=r"(r[1]) : "r"(addr));
}
__device__ __forceinline__ void mma_bf16(float* d, const uint32_t* a, const uint32_t* b) {
    asm volatile(
        "mma.sync.aligned.m16n8k16.row.col.f32.bf16.bf16.f32 "
        "{%0,%1,%2,%3}, {%4,%5,%6,%7}, {%8,%9}, {%0,%1,%2,%3};"
        : "+f"(d[0]), "+f"(d[1]), "+f"(d[2]), "+f"(d[3])
        : "r"(a[0]), "r"(a[1]), "r"(a[2]), "r"(a[3]), "r"(b[0]), "r"(b[1]));
}
__device__ __forceinline__ void mma_f16(float* d, const uint32_t* a, const uint32_t* b) {
    asm volatile(
        "mma.sync.aligned.m16n8k16.row.col.f32.f16.f16.f32 "
        "{%0,%1,%2,%3}, {%4,%5,%6,%7}, {%8,%9}, {%0,%1,%2,%3};"
        : "+f"(d[0]), "+f"(d[1]), "+f"(d[2]), "+f"(d[3])
        : "r"(a[0]), "r"(a[1]), "r"(a[2]), "r"(a[3]), "r"(b[0]), "r"(b[1]));
}
__device__ __forceinline__ void cpa16(uint32_t dst, const void* src) {
    asm volatile("cp.async.cg.shared.global [%0], [%1], 16;" :: "r"(dst), "l"(src));
}
#define CPA_COMMIT() asm volatile("cp.async.commit_group;" ::: "memory")
#define CPA_WAIT1()  asm volatile("cp.async.wait_group 1;" ::: "memory")
#define CPA_WAIT0()  asm volatile("cp.async.wait_group 0;" ::: "memory")

__device__ __forceinline__ uint32_t packbf(float a, float b) {
    __nv_bfloat162 t(__float2bfloat16_rn(a), __float2bfloat16_rn(b));
    return *reinterpret_cast<uint32_t*>(&t);
}
__device__ __forceinline__ uint32_t packh(float a, float b) {
    __half2 t(__float2half_rn(a), __float2half_rn(b));
    return *reinterpret_cast<uint32_t*>(&t);
}

// ---------------------------------------------------------------------------
// Fused split: all 7 tensors in one launch (blockIdx.y = job).
// ---------------------------------------------------------------------------
__global__ void split_all(const float* __restrict__ q, const float* __restrict__ kt,
                          const float* __restrict__ v,
                          const float* __restrict__ qw, const float* __restrict__ kw,
                          const float* __restrict__ vw, const float* __restrict__ ow,
                          __nv_bfloat16* __restrict__ a0, __nv_bfloat16* __restrict__ a1,
                          __nv_bfloat16* __restrict__ a2, __nv_bfloat16* __restrict__ w0,
                          __nv_bfloat16* __restrict__ w1, __nv_bfloat16* __restrict__ w2,
                          __nv_bfloat16* __restrict__ w3)
{
    const int job = blockIdx.y;
    const float* X; __nv_bfloat16* Y; int rows, mode;
    switch (job) {
        case 0: X = q;  Y = a0; rows = NTOK; mode = 0; break;
        case 1: X = kt; Y = a1; rows = NTOK; mode = 0; break;
        case 2: X = v;  Y = a2; rows = NTOK; mode = 0; break;
        case 3: X = qw; Y = w0; rows = DIMM; mode = 1; break;
        case 4: X = kw; Y = w1; rows = DIMM; mode = 1; break;
        case 5: X = vw; Y = w2; rows = DIMM; mode = 1; break;
        default: X = ow; Y = w3; rows = DIMM; mode = 1; break;
    }
    const int nquads = rows * 192;
    int i = blockIdx.x * blockDim.x + threadIdx.x;
    if (i >= nquads) return;
    int r = i / 192;
    int k = (i % 192) * 4;
    float4 vv = *reinterpret_cast<const float4*>(&X[(size_t)r * DIMM + k]);
    float a[4] = {vv.x, vv.y, vv.z, vv.w};
    __nv_bfloat16 h[4], l[4];
#pragma unroll
    for (int e = 0; e < 4; e++) {
        h[e] = __float2bfloat16_rn(a[e]);
        l[e] = __float2bfloat16_rn(a[e] - __bfloat162float(h[e]));
    }
    uint2 hh, ll;
    {
        __nv_bfloat162 p0(h[0], h[1]), p1(h[2], h[3]);
        hh.x = *reinterpret_cast<uint32_t*>(&p0); hh.y = *reinterpret_cast<uint32_t*>(&p1);
        __nv_bfloat162 q0(l[0], l[1]), q1(l[2], l[3]);
        ll.x = *reinterpret_cast<uint32_t*>(&q0); ll.y = *reinterpret_cast<uint32_t*>(&q1);
    }
    size_t ro = (size_t)r * KB3;
    *reinterpret_cast<uint2*>(&Y[ro + k])            = hh;
    *reinterpret_cast<uint2*>(&Y[ro + DIMM + k])     = mode ? ll : hh;
    *reinterpret_cast<uint2*>(&Y[ro + 2 * DIMM + k]) = mode ? hh : ll;
}

// ---------------------------------------------------------------------------
// HMMA GEMM: BK=64, 3-stage cp.async, one barrier per stage, pitch 144.
// job: 0=Q->q_eff (bf16 split), 1=K->k_eff, 2=V->vt (fp16, transposed), 3=O->fp32
// ---------------------------------------------------------------------------
#define NST (KB3/64)     // 36
#define STG 3
#define GPITCH 144
#define STGB (128*GPITCH)
#define GSMEM (STG*2*STGB)

__global__ __launch_bounds__(256, 2)
void gemm_hmma(int zbase,
               const __nv_bfloat16* __restrict__ A0, const __nv_bfloat16* __restrict__ A1,
               const __nv_bfloat16* __restrict__ A2, const __nv_bfloat16* __restrict__ A3,
               const __nv_bfloat16* __restrict__ W0, const __nv_bfloat16* __restrict__ W1,
               const __nv_bfloat16* __restrict__ W2, const __nv_bfloat16* __restrict__ W3,
               const float* __restrict__ bq, const float* __restrict__ bk,
               const float* __restrict__ bv, const float* __restrict__ bo,
               float* __restrict__ outf,
               __nv_bfloat16* __restrict__ qe, __nv_bfloat16* __restrict__ kee,
               __half* __restrict__ vt)
{
    extern __shared__ unsigned char smg[];

    const int job = zbase + blockIdx.z;
    const __nv_bfloat16* A; const __nv_bfloat16* B; const float* bias;
    switch (job) {
        case 0: A = A0; B = W0; bias = bq; break;
        case 1: A = A1; B = W1; bias = bk; break;
        case 2: A = A2; B = W2; bias = bv; break;
        default: A = A3; B = W3; bias = bo; break;
    }

    const int tid    = threadIdx.x;
    const int lane   = tid & 31;
    const int wid    = tid >> 5;
    const int warp_m = wid & 1;
    const int warp_n = wid >> 1;
    const int bm = blockIdx.y * 128;
    const int bn = blockIdx.x * 128;

    const int lc  = tid & 7;
    const int lr0 = tid >> 3;
    const uint32_t smu = smem_u32(smg);

    float acc[4][4][4];
#pragma unroll
    for (int i = 0; i < 4; i++)
#pragma unroll
        for (int j = 0; j < 4; j++)
#pragma unroll
            for (int e = 0; e < 4; e++) acc[i][j][e] = 0.f;

    auto issue = [&](int s) {
        const size_t ke_ = (size_t)s * 64 + lc * 8;
        const uint32_t bo_ = (uint32_t)(s % STG) * (2 * STGB);
#pragma unroll
        for (int p = 0; p < 4; p++) {
            int r = lr0 + 32 * p;
            cpa16(smu + bo_ + r * GPITCH + lc * 16,         &A[(size_t)(bm + r) * KB3 + ke_]);
            cpa16(smu + bo_ + STGB + r * GPITCH + lc * 16,  &B[(size_t)(bn + r) * KB3 + ke_]);
        }
        CPA_COMMIT();
    };

    issue(0);
    issue(1);

    const int arow0 = warp_m * 64 + (lane & 15);
    const int acol  = (lane >> 4) * 16;
    const int brow0 = warp_n * 32 + (lane & 7);
    const int bcol  = ((lane >> 3) & 1) * 16;

    for (int s = 0; s < NST; s++) {
        if (s + 2 < NST) CPA_WAIT1(); else CPA_WAIT0();
        __syncthreads();
        if (s + 2 < NST) issue(s + 2);

        const uint32_t bo_ = (uint32_t)(s % STG) * (2 * STGB);
#pragma unroll
        for (int ks = 0; ks < 4; ks++) {
            uint32_t af[4][4], bf[4][2];
#pragma unroll
            for (int mt = 0; mt < 4; mt++)
                ldsm_x4(af[mt], smu + bo_ + (arow0 + mt * 16) * GPITCH + ks * 32 + acol);
#pragma unroll
            for (int nt = 0; nt < 4; nt++)
                ldsm_x2(bf[nt], smu + bo_ + STGB + (brow0 + nt * 8) * GPITCH + ks * 32 + bcol);
#pragma unroll
            for (int mt = 0; mt < 4; mt++)
#pragma unroll
                for (int nt = 0; nt < 4; nt++)
                    mma_bf16(acc[mt][nt], af[mt], bf[nt]);
        }
    }

    // ---- epilogue ----
    const int rbase = bm + warp_m * 64 + (lane >> 2);
    const int cbase = bn + warp_n * 32 + (lane & 3) * 2;
#pragma unroll
    for (int mt = 0; mt < 4; mt++) {
#pragma unroll
        for (int nt = 0; nt < 4; nt++) {
            const int col = cbase + nt * 8;
            const float b0 = bias[col], b1 = bias[col + 1];
            const int r0 = rbase + mt * 16;
#pragma unroll
            for (int rh = 0; rh < 2; rh++) {
                const int row = r0 + rh * 8;
                float x0 = acc[mt][nt][rh * 2 + 0] + b0;
                float x1 = acc[mt][nt][rh * 2 + 1] + b1;
                if (job == 3) {
                    float2 v = {x0, x1};
                    *reinterpret_cast<float2*>(&outf[(size_t)row * DIMM + col]) = v;
                } else {
                    const int b_  = row >> 11, pos = row & 2047;
                    const int h_  = col >> 6,  d   = col & 63;
                    if (job == 0) { x0 *= 0.125f; x1 *= 0.125f; }
                    if (job == 2) {
                        size_t base = ((size_t)(b_ * NH + h_) * DH + d) * SEQ + pos;
                        vt[base]       = __float2half_rn(x0);
                        vt[base + SEQ] = __float2half_rn(x1);
                    } else {
                        __nv_bfloat16 h0 = __float2bfloat16_rn(x0);
                        __nv_bfloat16 h1 = __float2bfloat16_rn(x1);
                        __nv_bfloat162 hhp(h0, h1);
                        uint32_t hh = *reinterpret_cast<uint32_t*>(&hhp);
                        uint32_t ll = packbf(x0 - __bfloat162float(h0),
                                             x1 - __bfloat162float(h1));
                        __nv_bfloat16* dst = (job == 0) ? qe : kee;
                        size_t base = ((size_t)(b_ * NH + h_) * SEQ + pos) * KE + d;
                        *reinterpret_cast<uint32_t*>(dst + base)       = hh;
                        *reinterpret_cast<uint32_t*>(dst + base + 64)  = (job == 0) ? hh : ll;
                        *reinterpret_cast<uint32_t*>(dst + base + 128) = (job == 0) ? ll : hh;
                    }
                }
            }
        }
    }
}

// ---------------------------------------------------------------------------
// HMMA flash attention. QK: 3-term bf16 (K=192). PV: single fp16 pass.
// ---------------------------------------------------------------------------
#define BR 256
#define BK 64
#define QP 400
#define VP 144
#define QS_OFF 0
#define KS_OFF 102400
#define KBUF   25600
#define VH_OFF 153600
#define VBUF   9216
#define MS_OFF 172032
#define ATT_SMEM 172544

__global__ __launch_bounds__(256)
void attn_hmma(const __nv_bfloat16* __restrict__ qe, const __nv_bfloat16* __restrict__ ke,
               const __half* __restrict__ vt,
               const int* __restrict__ mask, __nv_bfloat16* __restrict__ ctx)
{
    extern __shared__ unsigned char sm[];
    const uint32_t smb = smem_u32(sm);
    const int tid  = threadIdx.x;
    const int lane = tid & 31;
    const int wid  = tid >> 5;
    const int q0   = blockIdx.x * BR;
    const int bh   = blockIdx.y;
    const int b    = bh / NH;
    const int h    = bh - b * NH;

    const __nv_bfloat16* qg = qe + ((size_t)bh * SEQ + q0) * KE;
    for (int idx = tid; idx < BR * 24; idx += 256) {
        int row = idx / 24, ch = idx - row * 24;
        cpa16(smb + QS_OFF + row * QP + ch * 16,
              reinterpret_cast<const char*>(qg + (size_t)row * KE) + ch * 16);
    }

    auto load_tile = [&](int kt, int buf) {
        const int k0 = kt * BK;
        const __nv_bfloat16* kg = ke + ((size_t)bh * SEQ + k0) * KE;
        for (int idx = tid; idx < 64 * 24; idx += 256) {
            int r = idx / 24, ch = idx - r * 24;
            cpa16(smb + KS_OFF + buf * KBUF + r * QP + ch * 16,
                  reinterpret_cast<const char*>(kg + (size_t)r * KE) + ch * 16);
        }
        const size_t vg = (size_t)bh * DH * SEQ + k0;
        for (int idx = tid; idx < 64 * 8; idx += 256) {
            int d = idx >> 3, ch = idx & 7;
            cpa16(smb + VH_OFF + buf * VBUF + d * VP + ch * 16,
                  reinterpret_cast<const char*>(vt + vg + (size_t)d * SEQ) + ch * 16);
        }
        if (tid < 16)
            cpa16(smb + MS_OFF + buf * 256 + tid * 16,
                  reinterpret_cast<const char*>(mask + (size_t)b * SEQ + k0) + tid * 16);
    };

    load_tile(0, 0);
    CPA_COMMIT();

    float oacc[2][8][4];
    float m_[2][2], l_[2][2];
#pragma unroll
    for (int i = 0; i < 2; i++)
#pragma unroll
        for (int j = 0; j < 8; j++)
#pragma unroll
            for (int e = 0; e < 4; e++) oacc[i][j][e] = 0.f;
#pragma unroll
    for (int i = 0; i < 2; i++) { m_[i][0] = -1e30f; m_[i][1] = -1e30f; l_[i][0] = 0.f; l_[i][1] = 0.f; }

    const int l8  = lane & 7;
    const int ms1 = (lane >> 3) & 1;
    const int ms2 = (lane >> 4) & 1;
    const uint32_t qrowadr = smb + QS_OFF + (wid * 32 + l8 + ms1 * 8) * QP + ms2 * 16;
    const uint32_t krowadr0 = smb + KS_OFF + (l8 + ms1 * 8) * QP + ms2 * 16;
    const int l16 = lane & 15;
    const uint32_t vrowadr0 = smb + VH_OFF + (l16 & 7) * VP + ((l16 >> 3) * 16);
    const int qc = (lane & 3) * 2;
    const int* Msm = reinterpret_cast<const int*>(sm + MS_OFF);

    for (int kt = 0; kt < SEQ / BK; kt++) {
        const int buf = kt & 1;
        CPA_WAIT0();
        __syncthreads();
        if (kt + 1 < SEQ / BK) {
            load_tile(kt + 1, buf ^ 1);
            CPA_COMMIT();
        }

        // ---- S = Qeff @ Keff^T (bf16, K=192) ----
        float sacc[2][8][4];
#pragma unroll
        for (int i = 0; i < 2; i++)
#pragma unroll
            for (int j = 0; j < 8; j++)
#pragma unroll
                for (int e = 0; e < 4; e++) sacc[i][j][e] = 0.f;

#pragma unroll
        for (int ks = 0; ks < KE / 16; ks++) {
            uint32_t af[2][4], bf[8][2];
#pragma unroll
            for (int mi = 0; mi < 2; mi++)
                ldsm_x4(af[mi], qrowadr + mi * (16 * QP) + ks * 32);
#pragma unroll
            for (int j = 0; j < 4; j++) {
                uint32_t t4[4];
                ldsm_x4(t4, krowadr0 + buf * KBUF + j * (16 * QP) + ks * 32);
                bf[2 * j][0] = t4[0]; bf[2 * j][1] = t4[2];
                bf[2 * j + 1][0] = t4[1]; bf[2 * j + 1][1] = t4[3];
            }
#pragma unroll
            for (int n = 0; n < 8; n++)
#pragma unroll
                for (int mi = 0; mi < 2; mi++)
                    mma_bf16(sacc[mi][n], af[mi], bf[n]);
        }

        // ---- mask bias (hoisted: 8 x LDS.64 per warp-tile) ----
        const int mbase = buf * 64 + qc;
        float mb[8][2];
#pragma unroll
        for (int j = 0; j < 8; j++) {
            int2 mm = *reinterpret_cast<const int2*>(&Msm[mbase + j * 8]);
            mb[j][0] = mm.x ? 0.f : -1e30f;
            mb[j][1] = mm.y ? 0.f : -1e30f;
        }

        // ---- online softmax ----
#pragma unroll
        for (int mi = 0; mi < 2; mi++) {
#pragma unroll
            for (int rh = 0; rh < 2; rh++) {
                float mx = -1e30f;
#pragma unroll
                for (int j = 0; j < 8; j++) {
#pragma unroll
                    for (int c = 0; c < 2; c++) {
                        float v = sacc[mi][j][rh * 2 + c] + mb[j][c];
                        sacc[mi][j][rh * 2 + c] = v;
                        mx = fmaxf(mx, v);
                    }
                }
                mx = fmaxf(mx, __shfl_xor_sync(0xffffffffu, mx, 1));
                mx = fmaxf(mx, __shfl_xor_sync(0xffffffffu, mx, 2));
                const float mn = fmaxf(m_[mi][rh], mx);
                const float al = __expf(m_[mi][rh] - mn);
                float sum = 0.f;
#pragma unroll
                for (int j = 0; j < 8; j++) {
#pragma unroll
                    for (int c = 0; c < 2; c++) {
                        float p = __expf(sacc[mi][j][rh * 2 + c] - mn);
                        sacc[mi][j][rh * 2 + c] = p;
                        sum += p;
                    }
                }
                sum += __shfl_xor_sync(0xffffffffu, sum, 1);
                sum += __shfl_xor_sync(0xffffffffu, sum, 2);
                l_[mi][rh] = l_[mi][rh] * al + sum;
                m_[mi][rh] = mn;
#pragma unroll
                for (int j = 0; j < 8; j++) {
                    oacc[mi][j][rh * 2 + 0] *= al;
                    oacc[mi][j][rh * 2 + 1] *= al;
                }
            }
        }

        // ---- O += P @ V  (single fp16 pass, V-frag double buffered) ----
        uint32_t vbuf[2][8][2];
#pragma unroll
        for (int n = 0; n < 8; n++)
            ldsm_x2(vbuf[0][n], vrowadr0 + buf * VBUF + n * (8 * VP));
#pragma unroll
        for (int t = 0; t < 4; t++) {
            const int cur = t & 1;
            if (t < 3) {
#pragma unroll
                for (int n = 0; n < 8; n++)
                    ldsm_x2(vbuf[cur ^ 1][n], vrowadr0 + buf * VBUF + n * (8 * VP) + (t + 1) * 32);
            }
#pragma unroll
            for (int mi = 0; mi < 2; mi++) {
                uint32_t A16[4];
#pragma unroll
                for (int half = 0; half < 2; half++) {
                    const float* s4 = sacc[mi][2 * t + half];
                    A16[half * 2 + 0] = packh(s4[0], s4[1]);
                    A16[half * 2 + 1] = packh(s4[2], s4[3]);
                }
#pragma unroll
                for (int n = 0; n < 8; n++)
                    mma_f16(oacc[mi][n], A16, vbuf[cur][n]);
            }
        }
    }

    // ---- finalize: O/l, split to ctx_eff [hi,hi,lo] ----
#pragma unroll
    for (int mi = 0; mi < 2; mi++) {
#pragma unroll
        for (int rh = 0; rh < 2; rh++) {
            const int row = wid * 32 + mi * 16 + rh * 8 + (lane >> 2);
            const float inv = 1.f / l_[mi][rh];
            const size_t tb = (size_t)(b * SEQ + q0 + row) * KB3 + h * 64 + qc;
#pragma unroll
            for (int j = 0; j < 8; j++) {
                float x0 = oacc[mi][j][rh * 2 + 0] * inv;
                float x1 = oacc[mi][j][rh * 2 + 1] * inv;
                __nv_bfloat16 h0 = __float2bfloat16_rn(x0);
                __nv_bfloat16 h1 = __float2bfloat16_rn(x1);
                __nv_bfloat162 hp(h0, h1);
                uint32_t hh = *reinterpret_cast<uint32_t*>(&hp);
                uint32_t ll = packbf(x0 - __bfloat162float(h0), x1 - __bfloat162float(h1));
                __nv_bfloat16* dst = ctx + tb + j * 8;
                *reinterpret_cast<uint32_t*>(dst)            = hh;
                *reinterpret_cast<uint32_t*>(dst + DIMM)     = hh;
                *reinterpret_cast<uint32_t*>(dst + 2 * DIMM) = ll;
            }
        }
    }
}

// ---------------------------------------------------------------------------
extern "C" void kernel_launch(void* const* d_in, const int* in_sizes, int n_in,
                              void* d_out, int out_size)
{
    const float* query = (const float*)d_in[0];
    const float* key_t = (const float*)d_in[1];
    const float* value = (const float*)d_in[2];
    const int*   mask  = (const int*)  d_in[3];
    const float* q_w   = (const float*)d_in[4];
    const float* q_b   = (const float*)d_in[5];
    const float* k_w   = (const float*)d_in[6];
    const float* k_b   = (const float*)d_in[7];
    const float* v_w   = (const float*)d_in[8];
    const float* v_b   = (const float*)d_in[9];
    const float* o_w   = (const float*)d_in[10];
    const float* o_b   = (const float*)d_in[11];
    float* out = (float*)d_out;

    __nv_bfloat16 *a0, *a1, *a2, *w0, *w1, *w2, *w3, *gqe, *gke, *gce;
    __half* gvt;
    cudaGetSymbolAddress((void**)&a0, g_a0);
    cudaGetSymbolAddress((void**)&a1, g_a1);
    cudaGetSymbolAddress((void**)&a2, g_a2);
    cudaGetSymbolAddress((void**)&w0, g_w0);
    cudaGetSymbolAddress((void**)&w1, g_w1);
    cudaGetSymbolAddress((void**)&w2, g_w2);
    cudaGetSymbolAddress((void**)&w3, g_w3);
    cudaGetSymbolAddress((void**)&gqe, g_qe);
    cudaGetSymbolAddress((void**)&gke, g_ke);
    cudaGetSymbolAddress((void**)&gvt, g_vt);
    cudaGetSymbolAddress((void**)&gce, g_ce);

    cudaFuncSetAttribute(attn_hmma,
                         cudaFuncAttributeMaxDynamicSharedMemorySize, ATT_SMEM);
    cudaFuncSetAttribute(gemm_hmma,
                         cudaFuncAttributeMaxDynamicSharedMemorySize, GSMEM);

    split_all<<<dim3((NTOK * 192 + 255) / 256, 7), 256>>>(
        query, key_t, value, q_w, k_w, v_w, o_w, a0, a1, a2, w0, w1, w2, w3);

    gemm_hmma<<<dim3(DIMM / 128, NTOK / 128, 3), 256, GSMEM>>>(
        0, a0, a1, a2, gce, w0, w1, w2, w3, q_b, k_b, v_b, o_b,
        nullptr, gqe, gke, gvt);

    attn_hmma<<<dim3(SEQ / BR, BSZ * NH), 256, ATT_SMEM>>>(gqe, gke, gvt, mask, gce);

    gemm_hmma<<<dim3(DIMM / 128, NTOK / 128, 1), 256, GSMEM>>>(
        3, a0, a1, a2, gce, w0, w1, w2, w3, q_b, k_b, v_b, o_b,
        out, gqe, gke, gvt);
}

// round 8
// speedup vs baseline: 4.6988x; 1.3354x over previous
#include <cuda_runtime.h>
#include <cuda_bf16.h>
#include <cuda_fp16.h>
#include <math.h>
#include <cstdint>

#define BSZ  4
#define SEQ  2048
#define DIMM 768
#define NH   12
#define DH   64
#define NTOK (BSZ*SEQ)   // 8192
#define KB2  (2*DIMM)    // 1536: A'=[Ah,Al], W'=[Wh,Wh]  (fp16 2-term)
#define KE   128         // attention split head dim: [Qh64,Ql64] x [Kh64,Kh64]

// ---------------- scratch (device globals) ----------------------------------
__device__ __align__(256) __half g_a0 [(size_t)NTOK*KB2];
__device__ __align__(256) __half g_a1 [(size_t)NTOK*KB2];
__device__ __align__(256) __half g_a2 [(size_t)NTOK*KB2];
__device__ __align__(256) __half g_w0 [(size_t)DIMM*KB2];
__device__ __align__(256) __half g_w1 [(size_t)DIMM*KB2];
__device__ __align__(256) __half g_w2 [(size_t)DIMM*KB2];
__device__ __align__(256) __half g_w3 [(size_t)DIMM*KB2];
__device__ __align__(256) __half g_qe [(size_t)BSZ*NH*SEQ*KE];
__device__ __align__(256) __half g_ke [(size_t)BSZ*NH*SEQ*KE];
__device__ __align__(256) __half g_vt [(size_t)BSZ*NH*DH*SEQ];
__device__ __align__(256) __half g_ce [(size_t)NTOK*KB2];

// ---------------- helpers ---------------------------------------------------
__device__ __forceinline__ uint32_t smem_u32(const void* p) {
    uint32_t a;
    asm("{ .reg .u64 t; cvta.to.shared.u64 t, %1; cvt.u32.u64 %0, t; }" : "=r"(a) : "l"(p));
    return a;
}
__device__ __forceinline__ void ldsm_x4(uint32_t* r, uint32_t addr) {
    asm volatile("ldmatrix.sync.aligned.m8n8.x4.shared.b16 {%0,%1,%2,%3}, [%4];"
                 : "=r"(r[0]), "=r"(r[1]), "=r"(r[2]), "=r"(r[3]) : "r"(addr));
}
__device__ __forceinline__ void ldsm_x2(uint32_t* r, uint32_t addr) {
    asm volatile("ldmatrix.sync.aligned.m8n8.x2.shared.b16 {%0,%1}, [%2];"
                 : "=r"(r[0]), "=r"(r[1]) : "r"(addr));
}
__device__ __forceinline__ void mma_f16(float* d, const uint32_t* a, const uint32_t* b) {
    asm volatile(
        "mma.sync.aligned.m16n8k16.row.col.f32.f16.f16.f32 "
        "{%0,%1,%2,%3}, {%4,%5,%6,%7}, {%8,%9}, {%0,%1,%2,%3};"
        : "+f"(d[0]), "+f"(d[1]), "+f"(d[2]), "+f"(d[3])
        : "r"(a[0]), "r"(a[1]), "r"(a[2]), "r"(a[3]), "r"(b[0]), "r"(b[1]));
}
__device__ __forceinline__ void cpa16(uint32_t dst, const void* src) {
    asm volatile("cp.async.cg.shared.global [%0], [%1], 16;" :: "r"(dst), "l"(src));
}
#define CPA_COMMIT() asm volatile("cp.async.commit_group;" ::: "memory")
#define CPA_WAIT1()  asm volatile("cp.async.wait_group 1;" ::: "memory")
#define CPA_WAIT0()  asm volatile("cp.async.wait_group 0;" ::: "memory")

__device__ __forceinline__ uint32_t packh(float a, float b) {
    __half2 t(__float2half_rn(a), __float2half_rn(b));
    return *reinterpret_cast<uint32_t*>(&t);
}

// ---------------------------------------------------------------------------
// Fused split (fp16 2-term): all 7 tensors in one launch (blockIdx.y = job).
// activations (jobs 0-2): [hi, lo]; weights (jobs 3-6): [hi, hi]
// ---------------------------------------------------------------------------
__global__ void split_all(const float* __restrict__ q, const float* __restrict__ kt,
                          const float* __restrict__ v,
                          const float* __restrict__ qw, const float* __restrict__ kw,
                          const float* __restrict__ vw, const float* __restrict__ ow,
                          __half* __restrict__ a0, __half* __restrict__ a1,
                          __half* __restrict__ a2, __half* __restrict__ w0,
                          __half* __restrict__ w1, __half* __restrict__ w2,
                          __half* __restrict__ w3)
{
    const int job = blockIdx.y;
    const float* X; __half* Y; int rows, mode;
    switch (job) {
        case 0: X = q;  Y = a0; rows = NTOK; mode = 0; break;
        case 1: X = kt; Y = a1; rows = NTOK; mode = 0; break;
        case 2: X = v;  Y = a2; rows = NTOK; mode = 0; break;
        case 3: X = qw; Y = w0; rows = DIMM; mode = 1; break;
        case 4: X = kw; Y = w1; rows = DIMM; mode = 1; break;
        case 5: X = vw; Y = w2; rows = DIMM; mode = 1; break;
        default: X = ow; Y = w3; rows = DIMM; mode = 1; break;
    }
    const int nquads = rows * 192;
    int i = blockIdx.x * blockDim.x + threadIdx.x;
    if (i >= nquads) return;
    int r = i / 192;
    int k = (i % 192) * 4;
    float4 vv = *reinterpret_cast<const float4*>(&X[(size_t)r * DIMM + k]);
    float a[4] = {vv.x, vv.y, vv.z, vv.w};
    uint2 hh, ll;
    {
        __half h0 = __float2half_rn(a[0]), h1 = __float2half_rn(a[1]);
        __half h2 = __float2half_rn(a[2]), h3 = __float2half_rn(a[3]);
        __half2 p0(h0, h1), p1(h2, h3);
        hh.x = *reinterpret_cast<uint32_t*>(&p0); hh.y = *reinterpret_cast<uint32_t*>(&p1);
        if (!mode) {
            ll.x = packh(a[0] - __half2float(h0), a[1] - __half2float(h1));
            ll.y = packh(a[2] - __half2float(h2), a[3] - __half2float(h3));
        } else {
            ll = hh;
        }
    }
    size_t ro = (size_t)r * KB2;
    *reinterpret_cast<uint2*>(&Y[ro + k])        = hh;
    *reinterpret_cast<uint2*>(&Y[ro + DIMM + k]) = ll;
}

// ---------------------------------------------------------------------------
// HMMA fp16 GEMM: K=1536, BK=64, 3-stage cp.async, one barrier per stage.
// job: 0=Q->q_eff [Qh,Ql], 1=K->k_eff [Kh,Kh], 2=V->vt (fp16 transposed), 3=O->fp32
// ---------------------------------------------------------------------------
#define NST (KB2/64)     // 24
#define STG 3
#define GPITCH 144
#define STGB (128*GPITCH)
#define GSMEM (STG*2*STGB)

__global__ __launch_bounds__(256, 2)
void gemm_hmma(int zbase,
               const __half* __restrict__ A0, const __half* __restrict__ A1,
               const __half* __restrict__ A2, const __half* __restrict__ A3,
               const __half* __restrict__ W0, const __half* __restrict__ W1,
               const __half* __restrict__ W2, const __half* __restrict__ W3,
               const float* __restrict__ bq, const float* __restrict__ bk,
               const float* __restrict__ bv, const float* __restrict__ bo,
               float* __restrict__ outf,
               __half* __restrict__ qe, __half* __restrict__ kee,
               __half* __restrict__ vt)
{
    extern __shared__ unsigned char smg[];

    const int job = zbase + blockIdx.z;
    const __half* A; const __half* B; const float* bias;
    switch (job) {
        case 0: A = A0; B = W0; bias = bq; break;
        case 1: A = A1; B = W1; bias = bk; break;
        case 2: A = A2; B = W2; bias = bv; break;
        default: A = A3; B = W3; bias = bo; break;
    }

    const int tid    = threadIdx.x;
    const int lane   = tid & 31;
    const int wid    = tid >> 5;
    const int warp_m = wid & 1;
    const int warp_n = wid >> 1;
    const int bm = blockIdx.y * 128;
    const int bn = blockIdx.x * 128;

    const int lc  = tid & 7;
    const int lr0 = tid >> 3;
    const uint32_t smu = smem_u32(smg);

    float acc[4][4][4];
#pragma unroll
    for (int i = 0; i < 4; i++)
#pragma unroll
        for (int j = 0; j < 4; j++)
#pragma unroll
            for (int e = 0; e < 4; e++) acc[i][j][e] = 0.f;

    auto issue = [&](int s) {
        const size_t ke_ = (size_t)s * 64 + lc * 8;
        const uint32_t bo_ = (uint32_t)(s % STG) * (2 * STGB);
#pragma unroll
        for (int p = 0; p < 4; p++) {
            int r = lr0 + 32 * p;
            cpa16(smu + bo_ + r * GPITCH + lc * 16,         &A[(size_t)(bm + r) * KB2 + ke_]);
            cpa16(smu + bo_ + STGB + r * GPITCH + lc * 16,  &B[(size_t)(bn + r) * KB2 + ke_]);
        }
        CPA_COMMIT();
    };

    issue(0);
    issue(1);

    const int arow0 = warp_m * 64 + (lane & 15);
    const int acol  = (lane >> 4) * 16;
    const int brow0 = warp_n * 32 + (lane & 7);
    const int bcol  = ((lane >> 3) & 1) * 16;

    for (int s = 0; s < NST; s++) {
        if (s + 2 < NST) CPA_WAIT1(); else CPA_WAIT0();
        __syncthreads();
        if (s + 2 < NST) issue(s + 2);

        const uint32_t bo_ = (uint32_t)(s % STG) * (2 * STGB);
#pragma unroll
        for (int ks = 0; ks < 4; ks++) {
            uint32_t af[4][4], bf[4][2];
#pragma unroll
            for (int mt = 0; mt < 4; mt++)
                ldsm_x4(af[mt], smu + bo_ + (arow0 + mt * 16) * GPITCH + ks * 32 + acol);
#pragma unroll
            for (int nt = 0; nt < 4; nt++)
                ldsm_x2(bf[nt], smu + bo_ + STGB + (brow0 + nt * 8) * GPITCH + ks * 32 + bcol);
#pragma unroll
            for (int mt = 0; mt < 4; mt++)
#pragma unroll
                for (int nt = 0; nt < 4; nt++)
                    mma_f16(acc[mt][nt], af[mt], bf[nt]);
        }
    }

    // ---- epilogue ----
    const int rbase = bm + warp_m * 64 + (lane >> 2);
    const int cbase = bn + warp_n * 32 + (lane & 3) * 2;
#pragma unroll
    for (int mt = 0; mt < 4; mt++) {
#pragma unroll
        for (int nt = 0; nt < 4; nt++) {
            const int col = cbase + nt * 8;
            const float b0 = bias[col], b1 = bias[col + 1];
            const int r0 = rbase + mt * 16;
#pragma unroll
            for (int rh = 0; rh < 2; rh++) {
                const int row = r0 + rh * 8;
                float x0 = acc[mt][nt][rh * 2 + 0] + b0;
                float x1 = acc[mt][nt][rh * 2 + 1] + b1;
                if (job == 3) {
                    float2 v = {x0, x1};
                    *reinterpret_cast<float2*>(&outf[(size_t)row * DIMM + col]) = v;
                } else {
                    const int b_  = row >> 11, pos = row & 2047;
                    const int h_  = col >> 6,  d   = col & 63;
                    if (job == 0) { x0 *= 0.125f; x1 *= 0.125f; }
                    if (job == 2) {
                        size_t base = ((size_t)(b_ * NH + h_) * DH + d) * SEQ + pos;
                        vt[base]       = __float2half_rn(x0);
                        vt[base + SEQ] = __float2half_rn(x1);
                    } else {
                        __half h0 = __float2half_rn(x0);
                        __half h1 = __float2half_rn(x1);
                        __half2 hp(h0, h1);
                        uint32_t hh = *reinterpret_cast<uint32_t*>(&hp);
                        uint32_t second =
                            (job == 0) ? packh(x0 - __half2float(h0), x1 - __half2float(h1))
                                       : hh;
                        __half* dst = (job == 0) ? qe : kee;
                        size_t base = ((size_t)(b_ * NH + h_) * SEQ + pos) * KE + d;
                        *reinterpret_cast<uint32_t*>(dst + base)      = hh;
                        *reinterpret_cast<uint32_t*>(dst + base + 64) = second;
                    }
                }
            }
        }
    }
}

// ---------------------------------------------------------------------------
// HMMA flash attention (all fp16 operands).
// QK: K=128 ([Qh,Ql] x [Kh,Kh]); PV: single fp16 pass.
// ---------------------------------------------------------------------------
#define BR 256
#define BK 64
#define QP 272                 // 256B row + 16B shift (odd multiple of 16)
#define VP 144
#define QS_OFF 0               // 256*272 = 69632
#define KS_OFF 69632
#define KBUF   17408           // 64*272
#define VH_OFF 104448          // KS_OFF + 2*KBUF
#define VBUF   9216
#define MS_OFF 122880          // VH_OFF + 2*VBUF
#define ATT_SMEM 123392

__global__ __launch_bounds__(256)
void attn_hmma(const __half* __restrict__ qe, const __half* __restrict__ ke,
               const __half* __restrict__ vt,
               const int* __restrict__ mask, __half* __restrict__ ctx)
{
    extern __shared__ unsigned char sm[];
    const uint32_t smb = smem_u32(sm);
    const int tid  = threadIdx.x;
    const int lane = tid & 31;
    const int wid  = tid >> 5;
    const int q0   = blockIdx.x * BR;
    const int bh   = blockIdx.y;
    const int b    = bh / NH;
    const int h    = bh - b * NH;

    const __half* qg = qe + ((size_t)bh * SEQ + q0) * KE;
    for (int idx = tid; idx < BR * 16; idx += 256) {
        int row = idx >> 4, ch = idx & 15;
        cpa16(smb + QS_OFF + row * QP + ch * 16,
              reinterpret_cast<const char*>(qg + (size_t)row * KE) + ch * 16);
    }

    auto load_tile = [&](int kt, int buf) {
        const int k0 = kt * BK;
        const __half* kg = ke + ((size_t)bh * SEQ + k0) * KE;
        for (int idx = tid; idx < 64 * 16; idx += 256) {
            int r = idx >> 4, ch = idx & 15;
            cpa16(smb + KS_OFF + buf * KBUF + r * QP + ch * 16,
                  reinterpret_cast<const char*>(kg + (size_t)r * KE) + ch * 16);
        }
        const size_t vg = (size_t)bh * DH * SEQ + k0;
        for (int idx = tid; idx < 64 * 8; idx += 256) {
            int d = idx >> 3, ch = idx & 7;
            cpa16(smb + VH_OFF + buf * VBUF + d * VP + ch * 16,
                  reinterpret_cast<const char*>(vt + vg + (size_t)d * SEQ) + ch * 16);
        }
        if (tid < 16)
            cpa16(smb + MS_OFF + buf * 256 + tid * 16,
                  reinterpret_cast<const char*>(mask + (size_t)b * SEQ + k0) + tid * 16);
    };

    load_tile(0, 0);
    CPA_COMMIT();

    float oacc[2][8][4];
    float m_[2][2], l_[2][2];
#pragma unroll
    for (int i = 0; i < 2; i++)
#pragma unroll
        for (int j = 0; j < 8; j++)
#pragma unroll
            for (int e = 0; e < 4; e++) oacc[i][j][e] = 0.f;
#pragma unroll
    for (int i = 0; i < 2; i++) { m_[i][0] = -1e30f; m_[i][1] = -1e30f; l_[i][0] = 0.f; l_[i][1] = 0.f; }

    const int l8  = lane & 7;
    const int ms1 = (lane >> 3) & 1;
    const int ms2 = (lane >> 4) & 1;
    const uint32_t qrowadr = smb + QS_OFF + (wid * 32 + l8 + ms1 * 8) * QP + ms2 * 16;
    const uint32_t krowadr0 = smb + KS_OFF + (l8 + ms1 * 8) * QP + ms2 * 16;
    const int l16 = lane & 15;
    const uint32_t vrowadr0 = smb + VH_OFF + (l16 & 7) * VP + ((l16 >> 3) * 16);
    const int qc = (lane & 3) * 2;
    const int* Msm = reinterpret_cast<const int*>(sm + MS_OFF);

    for (int kt = 0; kt < SEQ / BK; kt++) {
        const int buf = kt & 1;
        CPA_WAIT0();
        __syncthreads();
        if (kt + 1 < SEQ / BK) {
            load_tile(kt + 1, buf ^ 1);
            CPA_COMMIT();
        }

        // ---- S = Qeff @ Keff^T (fp16, K=128) ----
        float sacc[2][8][4];
#pragma unroll
        for (int i = 0; i < 2; i++)
#pragma unroll
            for (int j = 0; j < 8; j++)
#pragma unroll
                for (int e = 0; e < 4; e++) sacc[i][j][e] = 0.f;

#pragma unroll
        for (int ks = 0; ks < KE / 16; ks++) {
            uint32_t af[2][4], bf[8][2];
#pragma unroll
            for (int mi = 0; mi < 2; mi++)
                ldsm_x4(af[mi], qrowadr + mi * (16 * QP) + ks * 32);
#pragma unroll
            for (int j = 0; j < 4; j++) {
                uint32_t t4[4];
                ldsm_x4(t4, krowadr0 + buf * KBUF + j * (16 * QP) + ks * 32);
                bf[2 * j][0] = t4[0]; bf[2 * j][1] = t4[2];
                bf[2 * j + 1][0] = t4[1]; bf[2 * j + 1][1] = t4[3];
            }
#pragma unroll
            for (int n = 0; n < 8; n++)
#pragma unroll
                for (int mi = 0; mi < 2; mi++)
                    mma_f16(sacc[mi][n], af[mi], bf[n]);
        }

        // ---- mask bias (hoisted) ----
        const int mbase = buf * 64 + qc;
        float mb[8][2];
#pragma unroll
        for (int j = 0; j < 8; j++) {
            int2 mm = *reinterpret_cast<const int2*>(&Msm[mbase + j * 8]);
            mb[j][0] = mm.x ? 0.f : -1e30f;
            mb[j][1] = mm.y ? 0.f : -1e30f;
        }

        // ---- online softmax ----
#pragma unroll
        for (int mi = 0; mi < 2; mi++) {
#pragma unroll
            for (int rh = 0; rh < 2; rh++) {
                float mx = -1e30f;
#pragma unroll
                for (int j = 0; j < 8; j++) {
#pragma unroll
                    for (int c = 0; c < 2; c++) {
                        float v = sacc[mi][j][rh * 2 + c] + mb[j][c];
                        sacc[mi][j][rh * 2 + c] = v;
                        mx = fmaxf(mx, v);
                    }
                }
                mx = fmaxf(mx, __shfl_xor_sync(0xffffffffu, mx, 1));
                mx = fmaxf(mx, __shfl_xor_sync(0xffffffffu, mx, 2));
                const float mn = fmaxf(m_[mi][rh], mx);
                const float al = __expf(m_[mi][rh] - mn);
                float sum = 0.f;
#pragma unroll
                for (int j = 0; j < 8; j++) {
#pragma unroll
                    for (int c = 0; c < 2; c++) {
                        float p = __expf(sacc[mi][j][rh * 2 + c] - mn);
                        sacc[mi][j][rh * 2 + c] = p;
                        sum += p;
                    }
                }
                sum += __shfl_xor_sync(0xffffffffu, sum, 1);
                sum += __shfl_xor_sync(0xffffffffu, sum, 2);
                l_[mi][rh] = l_[mi][rh] * al + sum;
                m_[mi][rh] = mn;
#pragma unroll
                for (int j = 0; j < 8; j++) {
                    oacc[mi][j][rh * 2 + 0] *= al;
                    oacc[mi][j][rh * 2 + 1] *= al;
                }
            }
        }

        // ---- O += P @ V (single fp16 pass, V-frag double buffered) ----
        uint32_t vbuf[2][8][2];
#pragma unroll
        for (int n = 0; n < 8; n++)
            ldsm_x2(vbuf[0][n], vrowadr0 + buf * VBUF + n * (8 * VP));
#pragma unroll
        for (int t = 0; t < 4; t++) {
            const int cur = t & 1;
            if (t < 3) {
#pragma unroll
                for (int n = 0; n < 8; n++)
                    ldsm_x2(vbuf[cur ^ 1][n], vrowadr0 + buf * VBUF + n * (8 * VP) + (t + 1) * 32);
            }
#pragma unroll
            for (int mi = 0; mi < 2; mi++) {
                uint32_t A16[4];
#pragma unroll
                for (int half = 0; half < 2; half++) {
                    const float* s4 = sacc[mi][2 * t + half];
                    A16[half * 2 + 0] = packh(s4[0], s4[1]);
                    A16[half * 2 + 1] = packh(s4[2], s4[3]);
                }
#pragma unroll
                for (int n = 0; n < 8; n++)
                    mma_f16(oacc[mi][n], A16, vbuf[cur][n]);
            }
        }
    }

    // ---- finalize: O/l, fp16 2-term split into ctx [Ch | Cl] ----
#pragma unroll
    for (int mi = 0; mi < 2; mi++) {
#pragma unroll
        for (int rh = 0; rh < 2; rh++) {
            const int row = wid * 32 + mi * 16 + rh * 8 + (lane >> 2);
            const float inv = 1.f / l_[mi][rh];
            const size_t tb = (size_t)(b * SEQ + q0 + row) * KB2 + h * 64 + qc;
#pragma unroll
            for (int j = 0; j < 8; j++) {
                float x0 = oacc[mi][j][rh * 2 + 0] * inv;
                float x1 = oacc[mi][j][rh * 2 + 1] * inv;
                __half h0 = __float2half_rn(x0);
                __half h1 = __float2half_rn(x1);
                __half2 hp(h0, h1);
                uint32_t hh = *reinterpret_cast<uint32_t*>(&hp);
                uint32_t ll = packh(x0 - __half2float(h0), x1 - __half2float(h1));
                __half* dst = ctx + tb + j * 8;
                *reinterpret_cast<uint32_t*>(dst)        = hh;
                *reinterpret_cast<uint32_t*>(dst + DIMM) = ll;
            }
        }
    }
}

// ---------------------------------------------------------------------------
extern "C" void kernel_launch(void* const* d_in, const int* in_sizes, int n_in,
                              void* d_out, int out_size)
{
    const float* query = (const float*)d_in[0];
    const float* key_t = (const float*)d_in[1];
    const float* value = (const float*)d_in[2];
    const int*   mask  = (const int*)  d_in[3];
    const float* q_w   = (const float*)d_in[4];
    const float* q_b   = (const float*)d_in[5];
    const float* k_w   = (const float*)d_in[6];
    const float* k_b   = (const float*)d_in[7];
    const float* v_w   = (const float*)d_in[8];
    const float* v_b   = (const float*)d_in[9];
    const float* o_w   = (const float*)d_in[10];
    const float* o_b   = (const float*)d_in[11];
    float* out = (float*)d_out;

    __half *a0, *a1, *a2, *w0, *w1, *w2, *w3, *gqe, *gke, *gvt, *gce;
    cudaGetSymbolAddress((void**)&a0, g_a0);
    cudaGetSymbolAddress((void**)&a1, g_a1);
    cudaGetSymbolAddress((void**)&a2, g_a2);
    cudaGetSymbolAddress((void**)&w0, g_w0);
    cudaGetSymbolAddress((void**)&w1, g_w1);
    cudaGetSymbolAddress((void**)&w2, g_w2);
    cudaGetSymbolAddress((void**)&w3, g_w3);
    cudaGetSymbolAddress((void**)&gqe, g_qe);
    cudaGetSymbolAddress((void**)&gke, g_ke);
    cudaGetSymbolAddress((void**)&gvt, g_vt);
    cudaGetSymbolAddress((void**)&gce, g_ce);

    cudaFuncSetAttribute(attn_hmma,
                         cudaFuncAttributeMaxDynamicSharedMemorySize, ATT_SMEM);
    cudaFuncSetAttribute(gemm_hmma,
                         cudaFuncAttributeMaxDynamicSharedMemorySize, GSMEM);

    split_all<<<dim3((NTOK * 192 + 255) / 256, 7), 256>>>(
        query, key_t, value, q_w, k_w, v_w, o_w, a0, a1, a2, w0, w1, w2, w3);

    gemm_hmma<<<dim3(DIMM / 128, NTOK / 128, 3), 256, GSMEM>>>(
        0, a0, a1, a2, gce, w0, w1, w2, w3, q_b, k_b, v_b, o_b,
        nullptr, gqe, gke, gvt);

    attn_hmma<<<dim3(SEQ / BR, BSZ * NH), 256, ATT_SMEM>>>(gqe, gke, gvt, mask, gce);

    gemm_hmma<<<dim3(DIMM / 128, NTOK / 128, 1), 256, GSMEM>>>(
        3, a0, a1, a2, gce, w0, w1, w2, w3, q_b, k_b, v_b, o_b,
        out, gqe, gke, gvt);
}